// round 2
// baseline (speedup 1.0000x reference)
#include <cuda_runtime.h>
#include <cuda_bf16.h>
#include <cstdint>

#define C_DIM 1024
#define NH 16
#define HD 64
#define MAX_T 8192
#define LMAX 1024
#define EPS_RMS 1.1920929e-07f

// Scratch (device globals: allocation-free rule)
__device__ float g_q[MAX_T * C_DIM];
__device__ float g_k[MAX_T * C_DIM];
__device__ float g_v[MAX_T * C_DIM];
__device__ float g_att[MAX_T * C_DIM];

// ---------------------------------------------------------------------------
// SGEMM: C[m][n] = sum_k A[m][k] * B[n][k] + bias[n]
// BM=BN=128, BK=8, 256 threads, 8x8 per-thread tile
// ---------------------------------------------------------------------------
__global__ __launch_bounds__(256) void sgemm_abt_bias(
    const float* __restrict__ A, const float* __restrict__ B,
    const float* __restrict__ bias, float* __restrict__ C,
    int M, int N, int K)
{
    __shared__ float As[8][128];
    __shared__ float Bs[8][128];
    const int tid = threadIdx.x;
    const int tx = tid & 15;   // col group 0..15
    const int ty = tid >> 4;   // row group 0..15
    const int row0 = blockIdx.y * 128;
    const int col0 = blockIdx.x * 128;

    const int lrow = tid >> 1;        // 0..127
    const int lk   = (tid & 1) * 4;   // 0 or 4

    const int arow = min(row0 + lrow, M - 1);
    const float* Aptr = A + (size_t)arow * K + lk;
    const float* Bptr = B + (size_t)(col0 + lrow) * K + lk;

    float acc[8][8];
#pragma unroll
    for (int i = 0; i < 8; i++)
#pragma unroll
        for (int j = 0; j < 8; j++) acc[i][j] = 0.0f;

    for (int k0 = 0; k0 < K; k0 += 8) {
        float4 av = *(const float4*)(Aptr + k0);
        float4 bv = *(const float4*)(Bptr + k0);
        __syncthreads();
        As[lk + 0][lrow] = av.x; As[lk + 1][lrow] = av.y;
        As[lk + 2][lrow] = av.z; As[lk + 3][lrow] = av.w;
        Bs[lk + 0][lrow] = bv.x; Bs[lk + 1][lrow] = bv.y;
        Bs[lk + 2][lrow] = bv.z; Bs[lk + 3][lrow] = bv.w;
        __syncthreads();
#pragma unroll
        for (int kk = 0; kk < 8; kk++) {
            float a[8], b[8];
            *(float4*)(a)     = *(const float4*)(&As[kk][ty * 4]);
            *(float4*)(a + 4) = *(const float4*)(&As[kk][64 + ty * 4]);
            *(float4*)(b)     = *(const float4*)(&Bs[kk][tx * 4]);
            *(float4*)(b + 4) = *(const float4*)(&Bs[kk][64 + tx * 4]);
#pragma unroll
            for (int i = 0; i < 8; i++)
#pragma unroll
                for (int j = 0; j < 8; j++)
                    acc[i][j] = fmaf(a[i], b[j], acc[i][j]);
        }
    }

#pragma unroll
    for (int i = 0; i < 8; i++) {
        int row = row0 + ((i < 4) ? (ty * 4 + i) : (64 + ty * 4 + i - 4));
        if (row < M) {
#pragma unroll
            for (int jh = 0; jh < 2; jh++) {
                int col = col0 + jh * 64 + tx * 4;
                float4 o;
                o.x = acc[i][jh * 4 + 0] + bias[col + 0];
                o.y = acc[i][jh * 4 + 1] + bias[col + 1];
                o.z = acc[i][jh * 4 + 2] + bias[col + 2];
                o.w = acc[i][jh * 4 + 3] + bias[col + 3];
                *(float4*)(&C[(size_t)row * N + col]) = o;
            }
        }
    }
}

// ---------------------------------------------------------------------------
// RMSNorm over head dim (64), one warp per row
// ---------------------------------------------------------------------------
__global__ __launch_bounds__(256) void rmsnorm_kernel(
    float* __restrict__ h, const float* __restrict__ w, int nrows)
{
    int row = blockIdx.x * (blockDim.x >> 5) + (threadIdx.x >> 5);
    int lane = threadIdx.x & 31;
    if (row >= nrows) return;
    float* p = h + (size_t)row * HD;
    float2 x = ((float2*)p)[lane];
    float ss = x.x * x.x + x.y * x.y;
#pragma unroll
    for (int o = 16; o > 0; o >>= 1) ss += __shfl_xor_sync(0xffffffffu, ss, o);
    float r = rsqrtf(ss * (1.0f / HD) + EPS_RMS);
    float2 wv = ((const float2*)w)[lane];
    x.x *= r * wv.x;
    x.y *= r * wv.y;
    ((float2*)p)[lane] = x;
}

// ---------------------------------------------------------------------------
// Varlen bidirectional attention, flash-style online softmax.
// Grid: (nseq, NH, LMAX/QT). Block: 128 threads, 1 thread = 1 query.
// ---------------------------------------------------------------------------
#define QT 128
#define KT 32
__global__ __launch_bounds__(128) void attn_kernel(
    const int* __restrict__ cu, int T)
{
    const int seq = blockIdx.x;
    const int head = blockIdx.y;
    const int s0 = cu[seq];
    const int L = cu[seq + 1] - s0;
    const int q0 = blockIdx.z * QT;
    if (q0 >= L) return;

    const int tid = threadIdx.x;
    const int qi = q0 + tid;
    const bool active = (qi < L);
    const float scale = 0.125f;  // 1/sqrt(64)

    float4 qreg[16];
    if (active) {
        const float4* qp = (const float4*)(g_q + (size_t)(s0 + qi) * C_DIM + head * HD);
#pragma unroll
        for (int i = 0; i < 16; i++) {
            float4 t = qp[i];
            t.x *= scale; t.y *= scale; t.z *= scale; t.w *= scale;
            qreg[i] = t;
        }
    } else {
#pragma unroll
        for (int i = 0; i < 16; i++) qreg[i] = make_float4(0.f, 0.f, 0.f, 0.f);
    }

    __shared__ float4 Ksh[KT][16];
    __shared__ float4 Vsh[KT][16];

    float m = -1e30f, l = 0.0f;
    float4 acc[16];
#pragma unroll
    for (int i = 0; i < 16; i++) acc[i] = make_float4(0.f, 0.f, 0.f, 0.f);

    const int nkt = (L + KT - 1) / KT;
    for (int kt = 0; kt < nkt; kt++) {
        const int base = kt * KT;
        __syncthreads();
        // cooperative load of KT keys/values (KT*16 float4 each)
        for (int it = tid; it < KT * 16; it += 128) {
            int kj = it >> 4;
            int dd = it & 15;
            if (base + kj < L) {
                size_t off = (size_t)(s0 + base + kj) * C_DIM + head * HD + dd * 4;
                Ksh[kj][dd] = *(const float4*)(g_k + off);
                Vsh[kj][dd] = *(const float4*)(g_v + off);
            } else {
                Ksh[kj][dd] = make_float4(0.f, 0.f, 0.f, 0.f);
                Vsh[kj][dd] = make_float4(0.f, 0.f, 0.f, 0.f);
            }
        }
        __syncthreads();

        if (active) {
            float s[KT];
#pragma unroll
            for (int j = 0; j < KT; j++) {
                float sj = 0.0f;
#pragma unroll
                for (int dd = 0; dd < 16; dd++) {
                    float4 kv = Ksh[j][dd];
                    sj = fmaf(qreg[dd].x, kv.x, sj);
                    sj = fmaf(qreg[dd].y, kv.y, sj);
                    sj = fmaf(qreg[dd].z, kv.z, sj);
                    sj = fmaf(qreg[dd].w, kv.w, sj);
                }
                s[j] = (base + j < L) ? sj : -1e30f;
            }
            float mt = m;
#pragma unroll
            for (int j = 0; j < KT; j++) mt = fmaxf(mt, s[j]);
            float corr = __expf(m - mt);
            l *= corr;
#pragma unroll
            for (int dd = 0; dd < 16; dd++) {
                acc[dd].x *= corr; acc[dd].y *= corr;
                acc[dd].z *= corr; acc[dd].w *= corr;
            }
#pragma unroll
            for (int j = 0; j < KT; j++) {
                float p = __expf(s[j] - mt);
                l += p;
#pragma unroll
                for (int dd = 0; dd < 16; dd++) {
                    float4 vv = Vsh[j][dd];
                    acc[dd].x = fmaf(p, vv.x, acc[dd].x);
                    acc[dd].y = fmaf(p, vv.y, acc[dd].y);
                    acc[dd].z = fmaf(p, vv.z, acc[dd].z);
                    acc[dd].w = fmaf(p, vv.w, acc[dd].w);
                }
            }
            m = mt;
        }
    }

    if (active) {
        float inv = 1.0f / l;
        float4* op = (float4*)(g_att + (size_t)(s0 + qi) * C_DIM + head * HD);
#pragma unroll
        for (int dd = 0; dd < 16; dd++) {
            float4 o = acc[dd];
            o.x *= inv; o.y *= inv; o.z *= inv; o.w *= inv;
            op[dd] = o;
        }
    }
}

// ---------------------------------------------------------------------------
// Launch
// ---------------------------------------------------------------------------
extern "C" void kernel_launch(void* const* d_in, const int* in_sizes, int n_in,
                              void* d_out, int out_size)
{
    const float* x  = (const float*)d_in[0];
    const int* cu   = (const int*)d_in[1];
    const float* Wq = (const float*)d_in[2];
    const float* bq = (const float*)d_in[3];
    const float* Wk = (const float*)d_in[4];
    const float* bk = (const float*)d_in[5];
    const float* Wv = (const float*)d_in[6];
    const float* bv = (const float*)d_in[7];
    const float* qn = (const float*)d_in[8];
    const float* kn = (const float*)d_in[9];
    const float* Wo = (const float*)d_in[10];
    const float* bo = (const float*)d_in[11];
    float* out = (float*)d_out;

    const int T = in_sizes[0] / C_DIM;
    const int nseq = in_sizes[1] - 1;

    float *q_ptr, *k_ptr, *v_ptr, *att_ptr;
    cudaGetSymbolAddress((void**)&q_ptr, g_q);
    cudaGetSymbolAddress((void**)&k_ptr, g_k);
    cudaGetSymbolAddress((void**)&v_ptr, g_v);
    cudaGetSymbolAddress((void**)&att_ptr, g_att);

    dim3 gemm_grid(C_DIM / 128, (T + 127) / 128);
    dim3 gemm_block(256);

    sgemm_abt_bias<<<gemm_grid, gemm_block>>>(x, Wq, bq, q_ptr, T, C_DIM, C_DIM);
    sgemm_abt_bias<<<gemm_grid, gemm_block>>>(x, Wk, bk, k_ptr, T, C_DIM, C_DIM);
    sgemm_abt_bias<<<gemm_grid, gemm_block>>>(x, Wv, bv, v_ptr, T, C_DIM, C_DIM);

    int nrows = T * NH;
    int rn_blocks = (nrows + 7) / 8;
    rmsnorm_kernel<<<rn_blocks, 256>>>(q_ptr, qn, nrows);
    rmsnorm_kernel<<<rn_blocks, 256>>>(k_ptr, kn, nrows);

    dim3 attn_grid(nseq, NH, LMAX / QT);
    attn_kernel<<<attn_grid, 128>>>(cu, T);

    sgemm_abt_bias<<<gemm_grid, gemm_block>>>(att_ptr, Wo, bo, out, T, C_DIM, C_DIM);
}

// round 4
// speedup vs baseline: 1.4489x; 1.4489x over previous
#include <cuda_runtime.h>
#include <cuda_bf16.h>
#include <cstdint>

#define C_DIM 1024
#define NH 16
#define HD 64
#define MAX_T 8192
#define LMAX 1024
#define EPS_RMS 1.1920929e-07f

// ---------------- scratch (device globals; allocation-free rule) ----------
__device__ float g_q[MAX_T * C_DIM];
__device__ float g_k[MAX_T * C_DIM];
__device__ float g_v[MAX_T * C_DIM];
__device__ float g_att[MAX_T * C_DIM];

__device__ __nv_bfloat16 g_xh[MAX_T * C_DIM];
__device__ __nv_bfloat16 g_xl[MAX_T * C_DIM];
__device__ __nv_bfloat16 g_ath[MAX_T * C_DIM];
__device__ __nv_bfloat16 g_atl[MAX_T * C_DIM];
__device__ __nv_bfloat16 g_wqh[C_DIM * C_DIM];
__device__ __nv_bfloat16 g_wql[C_DIM * C_DIM];
__device__ __nv_bfloat16 g_wkh[C_DIM * C_DIM];
__device__ __nv_bfloat16 g_wkl[C_DIM * C_DIM];
__device__ __nv_bfloat16 g_wvh[C_DIM * C_DIM];
__device__ __nv_bfloat16 g_wvl[C_DIM * C_DIM];
__device__ __nv_bfloat16 g_woh[C_DIM * C_DIM];
__device__ __nv_bfloat16 g_wol[C_DIM * C_DIM];

// ---------------- helpers ---------------------------------------------
__device__ __forceinline__ uint32_t smem_u32(const void* p) {
    uint32_t a;
    asm("{ .reg .u64 t; cvta.to.shared.u64 t, %1; cvt.u32.u64 %0, t; }"
        : "=r"(a) : "l"(p));
    return a;
}

#define LDSM_X4(r0, r1, r2, r3, addr) \
    asm volatile("ldmatrix.sync.aligned.m8n8.x4.shared.b16 {%0,%1,%2,%3}, [%4];" \
                 : "=r"(r0), "=r"(r1), "=r"(r2), "=r"(r3) : "r"(addr))

#define MMA16816(d, a, b) \
    asm volatile("mma.sync.aligned.m16n8k16.row.col.f32.bf16.bf16.f32 " \
                 "{%0,%1,%2,%3}, {%4,%5,%6,%7}, {%8,%9}, {%0,%1,%2,%3};" \
                 : "+f"((d)[0]), "+f"((d)[1]), "+f"((d)[2]), "+f"((d)[3]) \
                 : "r"((a)[0]), "r"((a)[1]), "r"((a)[2]), "r"((a)[3]), \
                   "r"((b)[0]), "r"((b)[1]))

#define CP_ASYNC16(dst, src) \
    asm volatile("cp.async.cg.shared.global [%0], [%1], 16;" :: "r"(dst), "l"(src))
#define CP_COMMIT() asm volatile("cp.async.commit_group;" ::: "memory")
#define CP_WAIT(n)  asm volatile("cp.async.wait_group %0;" :: "n"(n) : "memory")

// ---------------------------------------------------------------------------
// fp32 -> (hi bf16, lo bf16) split
// ---------------------------------------------------------------------------
__global__ __launch_bounds__(256) void split_bf16(
    const float4* __restrict__ in, uint2* __restrict__ hi, uint2* __restrict__ lo, int n4)
{
    int i = blockIdx.x * blockDim.x + threadIdx.x;
    if (i >= n4) return;
    float4 v = in[i];
    __nv_bfloat16 h0 = __float2bfloat16(v.x);
    __nv_bfloat16 h1 = __float2bfloat16(v.y);
    __nv_bfloat16 h2 = __float2bfloat16(v.z);
    __nv_bfloat16 h3 = __float2bfloat16(v.w);
    __nv_bfloat16 l0 = __float2bfloat16(v.x - __bfloat162float(h0));
    __nv_bfloat16 l1 = __float2bfloat16(v.y - __bfloat162float(h1));
    __nv_bfloat16 l2 = __float2bfloat16(v.z - __bfloat162float(h2));
    __nv_bfloat16 l3 = __float2bfloat16(v.w - __bfloat162float(h3));
    uint2 H, L;
    H.x = (uint32_t)__bfloat16_as_ushort(h0) | ((uint32_t)__bfloat16_as_ushort(h1) << 16);
    H.y = (uint32_t)__bfloat16_as_ushort(h2) | ((uint32_t)__bfloat16_as_ushort(h3) << 16);
    L.x = (uint32_t)__bfloat16_as_ushort(l0) | ((uint32_t)__bfloat16_as_ushort(l1) << 16);
    L.y = (uint32_t)__bfloat16_as_ushort(l2) | ((uint32_t)__bfloat16_as_ushort(l3) << 16);
    hi[i] = H;
    lo[i] = L;
}

// ---------------------------------------------------------------------------
// mma.sync bf16x3 GEMM: C[m][n] = sum_k A[m][k]*B[n][k] + bias[n]
// BM=BN=128, BK=32, 256 threads (8 warps, 4x2), double-buffered cp.async.
// ---------------------------------------------------------------------------
#define BKg 32
#define NKT (C_DIM / BKg)            // 32
#define ASTRIDE 40                   // bf16 elems per smem row (80 B, conflict-free)
#define SUBTILE_B (128 * ASTRIDE * 2)  // 10240 B
#define STAGE_BYTES (4 * SUBTILE_B)    // 40960 B  (Ah, Al, Bh, Bl)
#define GEMM_SMEM (2 * STAGE_BYTES)    // 81920 B

__device__ __forceinline__ void load_stage_g(
    const __nv_bfloat16* __restrict__ Ah, const __nv_bfloat16* __restrict__ Al,
    const __nv_bfloat16* __restrict__ Bh, const __nv_bfloat16* __restrict__ Bl,
    uint32_t smem_stage, int m0, int n0, int k0, int M, int tid)
{
    const __nv_bfloat16* srcs[4] = {Ah, Al, Bh, Bl};
#pragma unroll
    for (int i = 0; i < 8; i++) {
        const int c = tid + i * 256;         // 0..2047
        const int sub = c >> 9;              // 0..3
        const int r = (c >> 2) & 127;        // row in tile
        const int cc = c & 3;                // 16B chunk in row
        int grow = (sub < 2 ? m0 : n0) + r;
        const int lim = (sub < 2) ? M : C_DIM;
        if (grow >= lim) grow = lim - 1;
        const void* g = srcs[sub] + (size_t)grow * C_DIM + k0 + cc * 8;
        const uint32_t d = smem_stage + sub * SUBTILE_B + r * (ASTRIDE * 2) + cc * 16;
        CP_ASYNC16(d, g);
    }
}

__global__ __launch_bounds__(256, 1)
void gemm_bf16x3(const __nv_bfloat16* __restrict__ Ah, const __nv_bfloat16* __restrict__ Al,
                 const __nv_bfloat16* __restrict__ Bh, const __nv_bfloat16* __restrict__ Bl,
                 const float* __restrict__ bias, float* __restrict__ C, int M)
{
    extern __shared__ char dsm[];
    const uint32_t sbase = smem_u32(dsm);
    const int tid = threadIdx.x;
    const int wid = tid >> 5;
    const int lane = tid & 31;
    const int wm = wid & 3;      // 0..3 along M
    const int wn = wid >> 2;     // 0..1 along N
    const int m0 = blockIdx.y * 128;
    const int n0 = blockIdx.x * 128;

    float acc[2][8][4];
#pragma unroll
    for (int i = 0; i < 2; i++)
#pragma unroll
        for (int j = 0; j < 8; j++)
#pragma unroll
            for (int r = 0; r < 4; r++) acc[i][j][r] = 0.0f;

    load_stage_g(Ah, Al, Bh, Bl, sbase, m0, n0, 0, M, tid);
    CP_COMMIT();
    load_stage_g(Ah, Al, Bh, Bl, sbase + STAGE_BYTES, m0, n0, BKg, M, tid);
    CP_COMMIT();

    // ldmatrix address components (constant per thread)
    const int a_row = (lane & 15);
    const int a_col = (lane >> 4) * 8;
    const int b_row = (lane & 7) + ((lane >> 4) & 1) * 8;
    const int b_col = ((lane >> 3) & 1) * 8;

    for (int kt = 0; kt < NKT; kt++) {
        if (kt < NKT - 1) { CP_WAIT(1); } else { CP_WAIT(0); }
        __syncthreads();
        const uint32_t st = sbase + (kt & 1) * STAGE_BYTES;

#pragma unroll
        for (int ph = 0; ph < 2; ph++) {
            const int koff = ph * 16;
            uint32_t af[2][2][4];
            uint32_t bf[2][8][2];
#pragma unroll
            for (int prod = 0; prod < 2; prod++) {
                const uint32_t abase = st + prod * SUBTILE_B;
#pragma unroll
                for (int mf = 0; mf < 2; mf++) {
                    const uint32_t addr = abase +
                        (uint32_t)((wm * 32 + mf * 16 + a_row) * (ASTRIDE * 2) +
                                   (koff + a_col) * 2);
                    LDSM_X4(af[prod][mf][0], af[prod][mf][1],
                            af[prod][mf][2], af[prod][mf][3], addr);
                }
                const uint32_t bbase = st + (2 + prod) * SUBTILE_B;
#pragma unroll
                for (int np = 0; np < 4; np++) {
                    uint32_t r0, r1, r2, r3;
                    const uint32_t addr = bbase +
                        (uint32_t)((wn * 64 + np * 16 + b_row) * (ASTRIDE * 2) +
                                   (koff + b_col) * 2);
                    LDSM_X4(r0, r1, r2, r3, addr);
                    bf[prod][np * 2][0] = r0;     bf[prod][np * 2][1] = r1;
                    bf[prod][np * 2 + 1][0] = r2; bf[prod][np * 2 + 1][1] = r3;
                }
            }
#pragma unroll
            for (int mf = 0; mf < 2; mf++)
#pragma unroll
                for (int nf = 0; nf < 8; nf++) {
                    MMA16816(acc[mf][nf], af[0][mf], bf[0][nf]);  // Ah*Bh
                    MMA16816(acc[mf][nf], af[0][mf], bf[1][nf]);  // Ah*Bl
                    MMA16816(acc[mf][nf], af[1][mf], bf[0][nf]);  // Al*Bh
                }
        }
        __syncthreads();
        if (kt + 2 < NKT) {
            load_stage_g(Ah, Al, Bh, Bl, sbase + (kt & 1) * STAGE_BYTES,
                         m0, n0, (kt + 2) * BKg, M, tid);
            CP_COMMIT();
        }
    }

    // epilogue
    const int rbase = m0 + wm * 32 + (lane >> 2);
    const int cbase = n0 + wn * 64 + (lane & 3) * 2;
#pragma unroll
    for (int mf = 0; mf < 2; mf++) {
#pragma unroll
        for (int half = 0; half < 2; half++) {
            const int row = rbase + mf * 16 + half * 8;
            if (row < M) {
#pragma unroll
                for (int nf = 0; nf < 8; nf++) {
                    const int col = cbase + nf * 8;
                    float2 o;
                    o.x = acc[mf][nf][half * 2 + 0] + bias[col];
                    o.y = acc[mf][nf][half * 2 + 1] + bias[col + 1];
                    *(float2*)(C + (size_t)row * C_DIM + col) = o;
                }
            }
        }
    }
}

// ---------------------------------------------------------------------------
// RMSNorm over head dim (64), one warp per row
// ---------------------------------------------------------------------------
__global__ __launch_bounds__(256) void rmsnorm_kernel(
    float* __restrict__ h, const float* __restrict__ w, int nrows)
{
    int row = blockIdx.x * (blockDim.x >> 5) + (threadIdx.x >> 5);
    int lane = threadIdx.x & 31;
    if (row >= nrows) return;
    float* p = h + (size_t)row * HD;
    float2 x = ((float2*)p)[lane];
    float ss = x.x * x.x + x.y * x.y;
#pragma unroll
    for (int o = 16; o > 0; o >>= 1) ss += __shfl_xor_sync(0xffffffffu, ss, o);
    float r = rsqrtf(ss * (1.0f / HD) + EPS_RMS);
    float2 wv = ((const float2*)w)[lane];
    x.x *= r * wv.x;
    x.y *= r * wv.y;
    ((float2*)p)[lane] = x;
}

// ---------------------------------------------------------------------------
// Varlen bidirectional attention, flash-style online softmax (fp32).
// ---------------------------------------------------------------------------
#define QT 128
#define KT 32
__global__ __launch_bounds__(128) void attn_kernel(const int* __restrict__ cu, int T)
{
    const int seq = blockIdx.x;
    const int head = blockIdx.y;
    const int s0 = cu[seq];
    const int L = cu[seq + 1] - s0;
    const int q0 = blockIdx.z * QT;
    if (q0 >= L) return;

    const int tid = threadIdx.x;
    const int qi = q0 + tid;
    const bool active = (qi < L);
    const float scale = 0.125f;

    float4 qreg[16];
    if (active) {
        const float4* qp = (const float4*)(g_q + (size_t)(s0 + qi) * C_DIM + head * HD);
#pragma unroll
        for (int i = 0; i < 16; i++) {
            float4 t = qp[i];
            t.x *= scale; t.y *= scale; t.z *= scale; t.w *= scale;
            qreg[i] = t;
        }
    } else {
#pragma unroll
        for (int i = 0; i < 16; i++) qreg[i] = make_float4(0.f, 0.f, 0.f, 0.f);
    }

    __shared__ float4 Ksh[KT][16];
    __shared__ float4 Vsh[KT][16];

    float m = -1e30f, l = 0.0f;
    float4 acc[16];
#pragma unroll
    for (int i = 0; i < 16; i++) acc[i] = make_float4(0.f, 0.f, 0.f, 0.f);

    const int nkt = (L + KT - 1) / KT;
    for (int kt = 0; kt < nkt; kt++) {
        const int base = kt * KT;
        __syncthreads();
        for (int it = tid; it < KT * 16; it += 128) {
            int kj = it >> 4;
            int dd = it & 15;
            if (base + kj < L) {
                size_t off = (size_t)(s0 + base + kj) * C_DIM + head * HD + dd * 4;
                Ksh[kj][dd] = *(const float4*)(g_k + off);
                Vsh[kj][dd] = *(const float4*)(g_v + off);
            } else {
                Ksh[kj][dd] = make_float4(0.f, 0.f, 0.f, 0.f);
                Vsh[kj][dd] = make_float4(0.f, 0.f, 0.f, 0.f);
            }
        }
        __syncthreads();

        if (active) {
            float s[KT];
#pragma unroll
            for (int j = 0; j < KT; j++) {
                float sj = 0.0f;
#pragma unroll
                for (int dd = 0; dd < 16; dd++) {
                    float4 kv = Ksh[j][dd];
                    sj = fmaf(qreg[dd].x, kv.x, sj);
                    sj = fmaf(qreg[dd].y, kv.y, sj);
                    sj = fmaf(qreg[dd].z, kv.z, sj);
                    sj = fmaf(qreg[dd].w, kv.w, sj);
                }
                s[j] = (base + j < L) ? sj : -1e30f;
            }
            float mt = m;
#pragma unroll
            for (int j = 0; j < KT; j++) mt = fmaxf(mt, s[j]);
            float corr = __expf(m - mt);
            l *= corr;
#pragma unroll
            for (int dd = 0; dd < 16; dd++) {
                acc[dd].x *= corr; acc[dd].y *= corr;
                acc[dd].z *= corr; acc[dd].w *= corr;
            }
#pragma unroll
            for (int j = 0; j < KT; j++) {
                float p = __expf(s[j] - mt);
                l += p;
#pragma unroll
                for (int dd = 0; dd < 16; dd++) {
                    float4 vv = Vsh[j][dd];
                    acc[dd].x = fmaf(p, vv.x, acc[dd].x);
                    acc[dd].y = fmaf(p, vv.y, acc[dd].y);
                    acc[dd].z = fmaf(p, vv.z, acc[dd].z);
                    acc[dd].w = fmaf(p, vv.w, acc[dd].w);
                }
            }
            m = mt;
        }
    }

    if (active) {
        float inv = 1.0f / l;
        float4* op = (float4*)(g_att + (size_t)(s0 + qi) * C_DIM + head * HD);
#pragma unroll
        for (int dd = 0; dd < 16; dd++) {
            float4 o = acc[dd];
            o.x *= inv; o.y *= inv; o.z *= inv; o.w *= inv;
            op[dd] = o;
        }
    }
}

// ---------------------------------------------------------------------------
// Launch
// ---------------------------------------------------------------------------
extern "C" void kernel_launch(void* const* d_in, const int* in_sizes, int n_in,
                              void* d_out, int out_size)
{
    const float* x  = (const float*)d_in[0];
    const int* cu   = (const int*)d_in[1];
    const float* Wq = (const float*)d_in[2];
    const float* bq = (const float*)d_in[3];
    const float* Wk = (const float*)d_in[4];
    const float* bk = (const float*)d_in[5];
    const float* Wv = (const float*)d_in[6];
    const float* bv = (const float*)d_in[7];
    const float* qn = (const float*)d_in[8];
    const float* kn = (const float*)d_in[9];
    const float* Wo = (const float*)d_in[10];
    const float* bo = (const float*)d_in[11];
    float* out = (float*)d_out;

    const int T = in_sizes[0] / C_DIM;
    const int nseq = in_sizes[1] - 1;

    float *q_ptr, *k_ptr, *v_ptr, *att_ptr;
    cudaGetSymbolAddress((void**)&q_ptr, g_q);
    cudaGetSymbolAddress((void**)&k_ptr, g_k);
    cudaGetSymbolAddress((void**)&v_ptr, g_v);
    cudaGetSymbolAddress((void**)&att_ptr, g_att);
    __nv_bfloat16 *xh, *xl, *ath, *atl, *wqh, *wql, *wkh, *wkl, *wvh, *wvl, *woh, *wol;
    cudaGetSymbolAddress((void**)&xh, g_xh);
    cudaGetSymbolAddress((void**)&xl, g_xl);
    cudaGetSymbolAddress((void**)&ath, g_ath);
    cudaGetSymbolAddress((void**)&atl, g_atl);
    cudaGetSymbolAddress((void**)&wqh, g_wqh);
    cudaGetSymbolAddress((void**)&wql, g_wql);
    cudaGetSymbolAddress((void**)&wkh, g_wkh);
    cudaGetSymbolAddress((void**)&wkl, g_wkl);
    cudaGetSymbolAddress((void**)&wvh, g_wvh);
    cudaGetSymbolAddress((void**)&wvl, g_wvl);
    cudaGetSymbolAddress((void**)&woh, g_woh);
    cudaGetSymbolAddress((void**)&wol, g_wol);

    cudaFuncSetAttribute(gemm_bf16x3, cudaFuncAttributeMaxDynamicSharedMemorySize,
                         GEMM_SMEM);

    // fp32 -> bf16 hi/lo splits
    const int xn4 = T * C_DIM / 4;
    const int wn4 = C_DIM * C_DIM / 4;
    split_bf16<<<(xn4 + 255) / 256, 256>>>((const float4*)x, (uint2*)xh, (uint2*)xl, xn4);
    split_bf16<<<(wn4 + 255) / 256, 256>>>((const float4*)Wq, (uint2*)wqh, (uint2*)wql, wn4);
    split_bf16<<<(wn4 + 255) / 256, 256>>>((const float4*)Wk, (uint2*)wkh, (uint2*)wkl, wn4);
    split_bf16<<<(wn4 + 255) / 256, 256>>>((const float4*)Wv, (uint2*)wvh, (uint2*)wvl, wn4);
    split_bf16<<<(wn4 + 255) / 256, 256>>>((const float4*)Wo, (uint2*)woh, (uint2*)wol, wn4);

    dim3 ggrid(C_DIM / 128, (T + 127) / 128);
    gemm_bf16x3<<<ggrid, 256, GEMM_SMEM>>>(xh, xl, wqh, wql, bq, q_ptr, T);
    gemm_bf16x3<<<ggrid, 256, GEMM_SMEM>>>(xh, xl, wkh, wkl, bk, k_ptr, T);
    gemm_bf16x3<<<ggrid, 256, GEMM_SMEM>>>(xh, xl, wvh, wvl, bv, v_ptr, T);

    int nrows = T * NH;
    int rn_blocks = (nrows + 7) / 8;
    rmsnorm_kernel<<<rn_blocks, 256>>>(q_ptr, qn, nrows);
    rmsnorm_kernel<<<rn_blocks, 256>>>(k_ptr, kn, nrows);

    dim3 attn_grid(nseq, NH, LMAX / QT);
    attn_kernel<<<attn_grid, 128>>>(cu, T);

    split_bf16<<<(xn4 + 255) / 256, 256>>>((const float4*)att_ptr, (uint2*)ath, (uint2*)atl, xn4);
    gemm_bf16x3<<<ggrid, 256, GEMM_SMEM>>>(ath, atl, woh, wol, bo, out, T);
}

// round 5
// speedup vs baseline: 2.5462x; 1.7573x over previous
#include <cuda_runtime.h>
#include <cuda_bf16.h>
#include <cstdint>

#define C_DIM 1024
#define NH 16
#define HD 64
#define MAX_T 8192
#define LMAX 1024
#define EPS_RMS 1.1920929e-07f

// ---------------- scratch (device globals; allocation-free rule) ----------
__device__ float g_q[MAX_T * C_DIM];
__device__ float g_k[MAX_T * C_DIM];

__device__ __nv_bfloat16 g_xh[MAX_T * C_DIM];
__device__ __nv_bfloat16 g_xl[MAX_T * C_DIM];
__device__ __nv_bfloat16 g_qh[MAX_T * C_DIM];
__device__ __nv_bfloat16 g_ql[MAX_T * C_DIM];
__device__ __nv_bfloat16 g_kh2[MAX_T * C_DIM];
__device__ __nv_bfloat16 g_kl2[MAX_T * C_DIM];
__device__ __nv_bfloat16 g_vh2[MAX_T * C_DIM];
__device__ __nv_bfloat16 g_vl2[MAX_T * C_DIM];
__device__ __nv_bfloat16 g_ath[MAX_T * C_DIM];
__device__ __nv_bfloat16 g_atl[MAX_T * C_DIM];
__device__ __nv_bfloat16 g_wqh[C_DIM * C_DIM];
__device__ __nv_bfloat16 g_wql[C_DIM * C_DIM];
__device__ __nv_bfloat16 g_wkh[C_DIM * C_DIM];
__device__ __nv_bfloat16 g_wkl[C_DIM * C_DIM];
__device__ __nv_bfloat16 g_wvh[C_DIM * C_DIM];
__device__ __nv_bfloat16 g_wvl[C_DIM * C_DIM];
__device__ __nv_bfloat16 g_woh[C_DIM * C_DIM];
__device__ __nv_bfloat16 g_wol[C_DIM * C_DIM];

// ---------------- helpers ---------------------------------------------
__device__ __forceinline__ uint32_t smem_u32(const void* p) {
    uint32_t a;
    asm("{ .reg .u64 t; cvta.to.shared.u64 t, %1; cvt.u32.u64 %0, t; }"
        : "=r"(a) : "l"(p));
    return a;
}

#define LDSM_X4(r0, r1, r2, r3, addr) \
    asm volatile("ldmatrix.sync.aligned.m8n8.x4.shared.b16 {%0,%1,%2,%3}, [%4];" \
                 : "=r"(r0), "=r"(r1), "=r"(r2), "=r"(r3) : "r"(addr))

#define LDSM_X4_T(r0, r1, r2, r3, addr) \
    asm volatile("ldmatrix.sync.aligned.m8n8.x4.trans.shared.b16 {%0,%1,%2,%3}, [%4];" \
                 : "=r"(r0), "=r"(r1), "=r"(r2), "=r"(r3) : "r"(addr))

#define MMA16816(d, a, b) \
    asm volatile("mma.sync.aligned.m16n8k16.row.col.f32.bf16.bf16.f32 " \
                 "{%0,%1,%2,%3}, {%4,%5,%6,%7}, {%8,%9}, {%0,%1,%2,%3};" \
                 : "+f"((d)[0]), "+f"((d)[1]), "+f"((d)[2]), "+f"((d)[3]) \
                 : "r"((a)[0]), "r"((a)[1]), "r"((a)[2]), "r"((a)[3]), \
                   "r"((b)[0]), "r"((b)[1]))

#define CP_ASYNC16(dst, src) \
    asm volatile("cp.async.cg.shared.global [%0], [%1], 16;" :: "r"(dst), "l"(src))
#define CP_COMMIT() asm volatile("cp.async.commit_group;" ::: "memory")
#define CP_WAIT(n)  asm volatile("cp.async.wait_group %0;" :: "n"(n) : "memory")

__device__ __forceinline__ void split2(float x, float y, uint32_t& h, uint32_t& l) {
    __nv_bfloat16 hx = __float2bfloat16(x);
    __nv_bfloat16 hy = __float2bfloat16(y);
    __nv_bfloat162 H; H.x = hx; H.y = hy;
    __nv_bfloat162 L;
    L.x = __float2bfloat16(x - __bfloat162float(hx));
    L.y = __float2bfloat16(y - __bfloat162float(hy));
    h = *(uint32_t*)&H;
    l = *(uint32_t*)&L;
}

// ---------------------------------------------------------------------------
// fp32 -> (hi bf16, lo bf16) split
// ---------------------------------------------------------------------------
__global__ __launch_bounds__(256) void split_bf16(
    const float4* __restrict__ in, uint2* __restrict__ hi, uint2* __restrict__ lo, int n4)
{
    int i = blockIdx.x * blockDim.x + threadIdx.x;
    if (i >= n4) return;
    float4 v = in[i];
    uint2 H, L;
    split2(v.x, v.y, H.x, L.x);
    split2(v.z, v.w, H.y, L.y);
    hi[i] = H;
    lo[i] = L;
}

// ---------------------------------------------------------------------------
// mma.sync bf16x3 GEMM: C[m][n] = sum_k A[m][k]*B[n][k] + bias[n]
// BM=BN=128, BK=32, 256 threads (8 warps, 4x2), double-buffered cp.async.
// SPLIT_OUT: write bf16 hi/lo arrays instead of fp32.
// ---------------------------------------------------------------------------
#define BKg 32
#define NKT (C_DIM / BKg)
#define ASTRIDE 40
#define SUBTILE_B (128 * ASTRIDE * 2)
#define STAGE_BYTES (4 * SUBTILE_B)
#define GEMM_SMEM (2 * STAGE_BYTES)

__device__ __forceinline__ void load_stage_g(
    const __nv_bfloat16* __restrict__ Ah, const __nv_bfloat16* __restrict__ Al,
    const __nv_bfloat16* __restrict__ Bh, const __nv_bfloat16* __restrict__ Bl,
    uint32_t smem_stage, int m0, int n0, int k0, int M, int tid)
{
    const __nv_bfloat16* srcs[4] = {Ah, Al, Bh, Bl};
#pragma unroll
    for (int i = 0; i < 8; i++) {
        const int c = tid + i * 256;
        const int sub = c >> 9;
        const int r = (c >> 2) & 127;
        const int cc = c & 3;
        int grow = (sub < 2 ? m0 : n0) + r;
        const int lim = (sub < 2) ? M : C_DIM;
        if (grow >= lim) grow = lim - 1;
        const void* g = srcs[sub] + (size_t)grow * C_DIM + k0 + cc * 8;
        const uint32_t d = smem_stage + sub * SUBTILE_B + r * (ASTRIDE * 2) + cc * 16;
        CP_ASYNC16(d, g);
    }
}

template <bool SPLIT_OUT>
__global__ __launch_bounds__(256, 1)
void gemm_bf16x3(const __nv_bfloat16* __restrict__ Ah, const __nv_bfloat16* __restrict__ Al,
                 const __nv_bfloat16* __restrict__ Bh, const __nv_bfloat16* __restrict__ Bl,
                 const float* __restrict__ bias, float* __restrict__ C,
                 __nv_bfloat16* __restrict__ Oh, __nv_bfloat16* __restrict__ Ol, int M)
{
    extern __shared__ char dsm[];
    const uint32_t sbase = smem_u32(dsm);
    const int tid = threadIdx.x;
    const int wid = tid >> 5;
    const int lane = tid & 31;
    const int wm = wid & 3;
    const int wn = wid >> 2;
    const int m0 = blockIdx.y * 128;
    const int n0 = blockIdx.x * 128;

    float acc[2][8][4];
#pragma unroll
    for (int i = 0; i < 2; i++)
#pragma unroll
        for (int j = 0; j < 8; j++)
#pragma unroll
            for (int r = 0; r < 4; r++) acc[i][j][r] = 0.0f;

    load_stage_g(Ah, Al, Bh, Bl, sbase, m0, n0, 0, M, tid);
    CP_COMMIT();
    load_stage_g(Ah, Al, Bh, Bl, sbase + STAGE_BYTES, m0, n0, BKg, M, tid);
    CP_COMMIT();

    const int a_row = (lane & 15);
    const int a_col = (lane >> 4) * 8;
    const int b_row = (lane & 7) + ((lane >> 4) & 1) * 8;
    const int b_col = ((lane >> 3) & 1) * 8;

    for (int kt = 0; kt < NKT; kt++) {
        if (kt < NKT - 1) { CP_WAIT(1); } else { CP_WAIT(0); }
        __syncthreads();
        const uint32_t st = sbase + (kt & 1) * STAGE_BYTES;

#pragma unroll
        for (int ph = 0; ph < 2; ph++) {
            const int koff = ph * 16;
            uint32_t af[2][2][4];
            uint32_t bf[2][8][2];
#pragma unroll
            for (int prod = 0; prod < 2; prod++) {
                const uint32_t abase = st + prod * SUBTILE_B;
#pragma unroll
                for (int mf = 0; mf < 2; mf++) {
                    const uint32_t addr = abase +
                        (uint32_t)((wm * 32 + mf * 16 + a_row) * (ASTRIDE * 2) +
                                   (koff + a_col) * 2);
                    LDSM_X4(af[prod][mf][0], af[prod][mf][1],
                            af[prod][mf][2], af[prod][mf][3], addr);
                }
                const uint32_t bbase = st + (2 + prod) * SUBTILE_B;
#pragma unroll
                for (int np = 0; np < 4; np++) {
                    uint32_t r0, r1, r2, r3;
                    const uint32_t addr = bbase +
                        (uint32_t)((wn * 64 + np * 16 + b_row) * (ASTRIDE * 2) +
                                   (koff + b_col) * 2);
                    LDSM_X4(r0, r1, r2, r3, addr);
                    bf[prod][np * 2][0] = r0;     bf[prod][np * 2][1] = r1;
                    bf[prod][np * 2 + 1][0] = r2; bf[prod][np * 2 + 1][1] = r3;
                }
            }
#pragma unroll
            for (int mf = 0; mf < 2; mf++)
#pragma unroll
                for (int nf = 0; nf < 8; nf++) {
                    MMA16816(acc[mf][nf], af[0][mf], bf[0][nf]);
                    MMA16816(acc[mf][nf], af[0][mf], bf[1][nf]);
                    MMA16816(acc[mf][nf], af[1][mf], bf[0][nf]);
                }
        }
        __syncthreads();
        if (kt + 2 < NKT) {
            load_stage_g(Ah, Al, Bh, Bl, sbase + (kt & 1) * STAGE_BYTES,
                         m0, n0, (kt + 2) * BKg, M, tid);
            CP_COMMIT();
        }
    }

    const int rbase = m0 + wm * 32 + (lane >> 2);
    const int cbase = n0 + wn * 64 + (lane & 3) * 2;
#pragma unroll
    for (int mf = 0; mf < 2; mf++) {
#pragma unroll
        for (int half = 0; half < 2; half++) {
            const int row = rbase + mf * 16 + half * 8;
            if (row < M) {
#pragma unroll
                for (int nf = 0; nf < 8; nf++) {
                    const int col = cbase + nf * 8;
                    float v0 = acc[mf][nf][half * 2 + 0] + bias[col];
                    float v1 = acc[mf][nf][half * 2 + 1] + bias[col + 1];
                    if (SPLIT_OUT) {
                        uint32_t h, l;
                        split2(v0, v1, h, l);
                        *(uint32_t*)(Oh + (size_t)row * C_DIM + col) = h;
                        *(uint32_t*)(Ol + (size_t)row * C_DIM + col) = l;
                    } else {
                        float2 o; o.x = v0; o.y = v1;
                        *(float2*)(C + (size_t)row * C_DIM + col) = o;
                    }
                }
            }
        }
    }
}

// ---------------------------------------------------------------------------
// RMSNorm over head dim (64) + optional scale + bf16 hi/lo split.
// One warp per (token, head) row.
// ---------------------------------------------------------------------------
__global__ __launch_bounds__(256) void rmsnorm_split(
    const float* __restrict__ src, const float* __restrict__ w,
    __nv_bfloat16* __restrict__ hi, __nv_bfloat16* __restrict__ lo,
    int nrows, float scale)
{
    int row = blockIdx.x * (blockDim.x >> 5) + (threadIdx.x >> 5);
    int lane = threadIdx.x & 31;
    if (row >= nrows) return;
    const float* p = src + (size_t)row * HD;
    float2 x = ((const float2*)p)[lane];
    float ss = x.x * x.x + x.y * x.y;
#pragma unroll
    for (int o = 16; o > 0; o >>= 1) ss += __shfl_xor_sync(0xffffffffu, ss, o);
    float r = rsqrtf(ss * (1.0f / HD) + EPS_RMS) * scale;
    float2 wv = ((const float2*)w)[lane];
    float v0 = x.x * r * wv.x;
    float v1 = x.y * r * wv.y;
    uint32_t h, l;
    split2(v0, v1, h, l);
    *(uint32_t*)(hi + (size_t)row * HD + lane * 2) = h;
    *(uint32_t*)(lo + (size_t)row * HD + lane * 2) = l;
}

// ---------------------------------------------------------------------------
// Tensorized varlen attention (flash-2 style, bf16x3 for QK^T and P*V).
// Block: 256 thr (8 warps), 128 queries/block (16 rows/warp), K-tiles of 64.
// ---------------------------------------------------------------------------
#define KSTRIDE_B 144                 // padded row bytes (64 bf16 + 8 pad)
#define ARR_B (64 * KSTRIDE_B)        // 9216 B per array
#define ATT_STAGE (4 * ARR_B)         // Kh, Kl, Vh, Vl = 36864 B
#define ATT_SMEM (2 * ATT_STAGE)      // 73728 B

__global__ __launch_bounds__(256) void attn_mma(const int* __restrict__ cu)
{
    const int seq = blockIdx.x;
    const int head = blockIdx.y;
    const int s0 = cu[seq];
    const int L = cu[seq + 1] - s0;
    const int q0 = blockIdx.z * 128;
    if (q0 >= L) return;

    extern __shared__ char sm[];
    const uint32_t sb = smem_u32(sm);
    const int tid = threadIdx.x;
    const int wid = tid >> 5;
    const int lane = tid & 31;
    const int colh = head * HD;

    // ---- Q fragments (persistent, loaded straight from gmem) ----
    uint32_t aQh[4][4], aQl[4][4];
    {
        int r0 = q0 + wid * 16 + (lane >> 2);
        int r1 = r0 + 8;
        if (r0 >= L) r0 = L - 1;
        if (r1 >= L) r1 = L - 1;
        const size_t b0 = (size_t)(s0 + r0) * C_DIM + colh + (lane & 3) * 2;
        const size_t b1 = (size_t)(s0 + r1) * C_DIM + colh + (lane & 3) * 2;
#pragma unroll
        for (int kc = 0; kc < 4; kc++) {
            aQh[kc][0] = *(const uint32_t*)(g_qh + b0 + kc * 16);
            aQh[kc][1] = *(const uint32_t*)(g_qh + b1 + kc * 16);
            aQh[kc][2] = *(const uint32_t*)(g_qh + b0 + kc * 16 + 8);
            aQh[kc][3] = *(const uint32_t*)(g_qh + b1 + kc * 16 + 8);
            aQl[kc][0] = *(const uint32_t*)(g_ql + b0 + kc * 16);
            aQl[kc][1] = *(const uint32_t*)(g_ql + b1 + kc * 16);
            aQl[kc][2] = *(const uint32_t*)(g_ql + b0 + kc * 16 + 8);
            aQl[kc][3] = *(const uint32_t*)(g_ql + b1 + kc * 16 + 8);
        }
    }

    float o[8][4];
#pragma unroll
    for (int i = 0; i < 8; i++)
#pragma unroll
        for (int j = 0; j < 4; j++) o[i][j] = 0.0f;
    float m0 = -1e30f, m1 = -1e30f, l0 = 0.0f, l1 = 0.0f;

    const int ntiles = (L + 63) >> 6;

    auto load_tile = [&](int t) {
        const uint32_t st = sb + (t & 1) * ATT_STAGE;
        const int kb = t * 64;
        const __nv_bfloat16* srcs[4] = {g_kh2, g_kl2, g_vh2, g_vl2};
#pragma unroll
        for (int i = 0; i < 8; i++) {
            int c = tid + i * 256;
            int arr = c >> 9;
            int r = (c >> 3) & 63;
            int cc = c & 7;
            int key = kb + r;
            if (key >= L) key = L - 1;
            const void* g = srcs[arr] + (size_t)(s0 + key) * C_DIM + colh + cc * 8;
            CP_ASYNC16(st + arr * ARR_B + r * KSTRIDE_B + cc * 16, g);
        }
    };

    load_tile(0);
    CP_COMMIT();

    for (int t = 0; t < ntiles; t++) {
        if (t + 1 < ntiles) { load_tile(t + 1); CP_COMMIT(); CP_WAIT(1); }
        else { CP_WAIT(0); }
        __syncthreads();
        const uint32_t st = sb + (t & 1) * ATT_STAGE;
        const int kb = t * 64;

        // ---- S = Q K^T (bf16x3) ----
        float s[8][4];
#pragma unroll
        for (int i = 0; i < 8; i++)
#pragma unroll
            for (int j = 0; j < 4; j++) s[i][j] = 0.0f;

        const int mat = lane >> 3;
#pragma unroll
        for (int kc = 0; kc < 4; kc++) {
#pragma unroll
            for (int pair = 0; pair < 4; pair++) {
                const int krow = (pair * 2 + (mat >> 1)) * 8 + (lane & 7);
                const uint32_t cb = (uint32_t)(kc * 32 + (mat & 1) * 16);
                uint32_t kh[4], kl[4];
                LDSM_X4(kh[0], kh[1], kh[2], kh[3], st + 0     + krow * KSTRIDE_B + cb);
                LDSM_X4(kl[0], kl[1], kl[2], kl[3], st + ARR_B + krow * KSTRIDE_B + cb);
                uint32_t bh0[2] = {kh[0], kh[1]}, bh1[2] = {kh[2], kh[3]};
                uint32_t bl0[2] = {kl[0], kl[1]}, bl1[2] = {kl[2], kl[3]};
                MMA16816(s[pair * 2],     aQh[kc], bh0);
                MMA16816(s[pair * 2],     aQh[kc], bl0);
                MMA16816(s[pair * 2],     aQl[kc], bh0);
                MMA16816(s[pair * 2 + 1], aQh[kc], bh1);
                MMA16816(s[pair * 2 + 1], aQh[kc], bl1);
                MMA16816(s[pair * 2 + 1], aQl[kc], bh1);
            }
        }

        // ---- mask invalid keys ----
        const int cb0 = (lane & 3) * 2;
#pragma unroll
        for (int nf = 0; nf < 8; nf++) {
            int colk = kb + nf * 8 + cb0;
            if (colk >= L)     { s[nf][0] = -1e30f; s[nf][2] = -1e30f; }
            if (colk + 1 >= L) { s[nf][1] = -1e30f; s[nf][3] = -1e30f; }
        }

        // ---- online softmax ----
        float mx0 = -1e30f, mx1 = -1e30f;
#pragma unroll
        for (int nf = 0; nf < 8; nf++) {
            mx0 = fmaxf(mx0, fmaxf(s[nf][0], s[nf][1]));
            mx1 = fmaxf(mx1, fmaxf(s[nf][2], s[nf][3]));
        }
        mx0 = fmaxf(mx0, __shfl_xor_sync(0xffffffffu, mx0, 1));
        mx0 = fmaxf(mx0, __shfl_xor_sync(0xffffffffu, mx0, 2));
        mx1 = fmaxf(mx1, __shfl_xor_sync(0xffffffffu, mx1, 1));
        mx1 = fmaxf(mx1, __shfl_xor_sync(0xffffffffu, mx1, 2));
        const float nm0 = fmaxf(m0, mx0);
        const float nm1 = fmaxf(m1, mx1);
        const float corr0 = __expf(m0 - nm0);
        const float corr1 = __expf(m1 - nm1);
        m0 = nm0; m1 = nm1;
        l0 *= corr0; l1 *= corr1;
#pragma unroll
        for (int nf = 0; nf < 8; nf++) {
            o[nf][0] *= corr0; o[nf][1] *= corr0;
            o[nf][2] *= corr1; o[nf][3] *= corr1;
        }
#pragma unroll
        for (int nf = 0; nf < 8; nf++) {
            s[nf][0] = __expf(s[nf][0] - m0);
            s[nf][1] = __expf(s[nf][1] - m0);
            s[nf][2] = __expf(s[nf][2] - m1);
            s[nf][3] = __expf(s[nf][3] - m1);
            l0 += s[nf][0] + s[nf][1];
            l1 += s[nf][2] + s[nf][3];
        }

        // ---- O += P V (bf16x3) ----
#pragma unroll
        for (int j = 0; j < 4; j++) {
            uint32_t ph[4], pl[4];
            split2(s[2 * j][0], s[2 * j][1], ph[0], pl[0]);
            split2(s[2 * j][2], s[2 * j][3], ph[1], pl[1]);
            split2(s[2 * j + 1][0], s[2 * j + 1][1], ph[2], pl[2]);
            split2(s[2 * j + 1][2], s[2 * j + 1][3], ph[3], pl[3]);
            const uint32_t vrow = (uint32_t)((j * 16 + (lane & 15)) * KSTRIDE_B +
                                             ((lane >> 4) << 3) * 2);
#pragma unroll
            for (int vp = 0; vp < 4; vp++) {
                const uint32_t addr = st + 2 * ARR_B + vrow + (uint32_t)(vp * 32);
                uint32_t vh[4], vl[4];
                LDSM_X4_T(vh[0], vh[1], vh[2], vh[3], addr);
                LDSM_X4_T(vl[0], vl[1], vl[2], vl[3], addr + ARR_B);
                uint32_t bh0[2] = {vh[0], vh[1]}, bh1[2] = {vh[2], vh[3]};
                uint32_t bl0[2] = {vl[0], vl[1]}, bl1[2] = {vl[2], vl[3]};
                MMA16816(o[vp * 2],     ph, bh0);
                MMA16816(o[vp * 2],     pl, bh0);
                MMA16816(o[vp * 2],     ph, bl0);
                MMA16816(o[vp * 2 + 1], ph, bh1);
                MMA16816(o[vp * 2 + 1], pl, bh1);
                MMA16816(o[vp * 2 + 1], ph, bl1);
            }
        }
        __syncthreads();
    }

    // ---- final normalize + bf16 hi/lo store ----
    l0 += __shfl_xor_sync(0xffffffffu, l0, 1);
    l0 += __shfl_xor_sync(0xffffffffu, l0, 2);
    l1 += __shfl_xor_sync(0xffffffffu, l1, 1);
    l1 += __shfl_xor_sync(0xffffffffu, l1, 2);
    const float inv0 = 1.0f / l0;
    const float inv1 = 1.0f / l1;
    const int r0 = q0 + wid * 16 + (lane >> 2);
    const int r1 = r0 + 8;
#pragma unroll
    for (int nf = 0; nf < 8; nf++) {
        const int col = colh + nf * 8 + (lane & 3) * 2;
        if (r0 < L) {
            uint32_t h, l;
            split2(o[nf][0] * inv0, o[nf][1] * inv0, h, l);
            *(uint32_t*)(g_ath + (size_t)(s0 + r0) * C_DIM + col) = h;
            *(uint32_t*)(g_atl + (size_t)(s0 + r0) * C_DIM + col) = l;
        }
        if (r1 < L) {
            uint32_t h, l;
            split2(o[nf][2] * inv1, o[nf][3] * inv1, h, l);
            *(uint32_t*)(g_ath + (size_t)(s0 + r1) * C_DIM + col) = h;
            *(uint32_t*)(g_atl + (size_t)(s0 + r1) * C_DIM + col) = l;
        }
    }
}

// ---------------------------------------------------------------------------
// Launch
// ---------------------------------------------------------------------------
extern "C" void kernel_launch(void* const* d_in, const int* in_sizes, int n_in,
                              void* d_out, int out_size)
{
    const float* x  = (const float*)d_in[0];
    const int* cu   = (const int*)d_in[1];
    const float* Wq = (const float*)d_in[2];
    const float* bq = (const float*)d_in[3];
    const float* Wk = (const float*)d_in[4];
    const float* bk = (const float*)d_in[5];
    const float* Wv = (const float*)d_in[6];
    const float* bv = (const float*)d_in[7];
    const float* qn = (const float*)d_in[8];
    const float* kn = (const float*)d_in[9];
    const float* Wo = (const float*)d_in[10];
    const float* bo = (const float*)d_in[11];
    float* out = (float*)d_out;

    const int T = in_sizes[0] / C_DIM;
    const int nseq = in_sizes[1] - 1;

    float *q_ptr, *k_ptr;
    cudaGetSymbolAddress((void**)&q_ptr, g_q);
    cudaGetSymbolAddress((void**)&k_ptr, g_k);
    __nv_bfloat16 *xh, *xl, *qh, *ql, *kh, *kl, *vh, *vl, *ath, *atl;
    __nv_bfloat16 *wqh, *wql, *wkh, *wkl, *wvh, *wvl, *woh, *wol;
    cudaGetSymbolAddress((void**)&xh, g_xh);
    cudaGetSymbolAddress((void**)&xl, g_xl);
    cudaGetSymbolAddress((void**)&qh, g_qh);
    cudaGetSymbolAddress((void**)&ql, g_ql);
    cudaGetSymbolAddress((void**)&kh, g_kh2);
    cudaGetSymbolAddress((void**)&kl, g_kl2);
    cudaGetSymbolAddress((void**)&vh, g_vh2);
    cudaGetSymbolAddress((void**)&vl, g_vl2);
    cudaGetSymbolAddress((void**)&ath, g_ath);
    cudaGetSymbolAddress((void**)&atl, g_atl);
    cudaGetSymbolAddress((void**)&wqh, g_wqh);
    cudaGetSymbolAddress((void**)&wql, g_wql);
    cudaGetSymbolAddress((void**)&wkh, g_wkh);
    cudaGetSymbolAddress((void**)&wkl, g_wkl);
    cudaGetSymbolAddress((void**)&wvh, g_wvh);
    cudaGetSymbolAddress((void**)&wvl, g_wvl);
    cudaGetSymbolAddress((void**)&woh, g_woh);
    cudaGetSymbolAddress((void**)&wol, g_wol);

    cudaFuncSetAttribute(gemm_bf16x3<false>, cudaFuncAttributeMaxDynamicSharedMemorySize,
                         GEMM_SMEM);
    cudaFuncSetAttribute(gemm_bf16x3<true>, cudaFuncAttributeMaxDynamicSharedMemorySize,
                         GEMM_SMEM);
    cudaFuncSetAttribute(attn_mma, cudaFuncAttributeMaxDynamicSharedMemorySize,
                         ATT_SMEM);

    // fp32 -> bf16 hi/lo splits
    const int xn4 = T * C_DIM / 4;
    const int wn4 = C_DIM * C_DIM / 4;
    split_bf16<<<(xn4 + 255) / 256, 256>>>((const float4*)x, (uint2*)xh, (uint2*)xl, xn4);
    split_bf16<<<(wn4 + 255) / 256, 256>>>((const float4*)Wq, (uint2*)wqh, (uint2*)wql, wn4);
    split_bf16<<<(wn4 + 255) / 256, 256>>>((const float4*)Wk, (uint2*)wkh, (uint2*)wkl, wn4);
    split_bf16<<<(wn4 + 255) / 256, 256>>>((const float4*)Wv, (uint2*)wvh, (uint2*)wvl, wn4);
    split_bf16<<<(wn4 + 255) / 256, 256>>>((const float4*)Wo, (uint2*)woh, (uint2*)wol, wn4);

    dim3 ggrid(C_DIM / 128, (T + 127) / 128);
    gemm_bf16x3<false><<<ggrid, 256, GEMM_SMEM>>>(xh, xl, wqh, wql, bq, q_ptr,
                                                  nullptr, nullptr, T);
    gemm_bf16x3<false><<<ggrid, 256, GEMM_SMEM>>>(xh, xl, wkh, wkl, bk, k_ptr,
                                                  nullptr, nullptr, T);
    gemm_bf16x3<true><<<ggrid, 256, GEMM_SMEM>>>(xh, xl, wvh, wvl, bv, nullptr,
                                                 vh, vl, T);

    const int nrows = T * NH;
    const int rn_blocks = (nrows + 7) / 8;
    rmsnorm_split<<<rn_blocks, 256>>>(q_ptr, qn, qh, ql, nrows, 0.125f);
    rmsnorm_split<<<rn_blocks, 256>>>(k_ptr, kn, kh, kl, nrows, 1.0f);

    dim3 attn_grid(nseq, NH, LMAX / 128);
    attn_mma<<<attn_grid, 256, ATT_SMEM>>>(cu);

    gemm_bf16x3<false><<<ggrid, 256, GEMM_SMEM>>>(ath, atl, woh, wol, bo, out,
                                                  nullptr, nullptr, T);
}

// round 6
// speedup vs baseline: 3.0615x; 1.2024x over previous
#include <cuda_runtime.h>
#include <cuda_bf16.h>
#include <cstdint>

#define C_DIM 1024
#define NH 16
#define HD 64
#define MAX_T 8192
#define LMAX 1024
#define EPS_RMS 1.1920929e-07f

typedef __nv_bfloat16 bf16;

// ---------------- scratch (device globals; allocation-free rule) ----------
__device__ float g_q[MAX_T * C_DIM];
__device__ float g_k[MAX_T * C_DIM];

__device__ bf16 g_xh[MAX_T * C_DIM];
__device__ bf16 g_xl[MAX_T * C_DIM];
__device__ bf16 g_qh[MAX_T * C_DIM];
__device__ bf16 g_ql[MAX_T * C_DIM];
__device__ bf16 g_kh2[MAX_T * C_DIM];
__device__ bf16 g_kl2[MAX_T * C_DIM];
__device__ bf16 g_vh2[MAX_T * C_DIM];
__device__ bf16 g_vl2[MAX_T * C_DIM];
__device__ bf16 g_ath[MAX_T * C_DIM];
__device__ bf16 g_atl[MAX_T * C_DIM];
__device__ bf16 g_wqh[C_DIM * C_DIM];
__device__ bf16 g_wql[C_DIM * C_DIM];
__device__ bf16 g_wkh[C_DIM * C_DIM];
__device__ bf16 g_wkl[C_DIM * C_DIM];
__device__ bf16 g_wvh[C_DIM * C_DIM];
__device__ bf16 g_wvl[C_DIM * C_DIM];
__device__ bf16 g_woh[C_DIM * C_DIM];
__device__ bf16 g_wol[C_DIM * C_DIM];

// ---------------- helpers ---------------------------------------------
__device__ __forceinline__ uint32_t smem_u32(const void* p) {
    uint32_t a;
    asm("{ .reg .u64 t; cvta.to.shared.u64 t, %1; cvt.u32.u64 %0, t; }"
        : "=r"(a) : "l"(p));
    return a;
}

#define LDSM_X4(r0, r1, r2, r3, addr) \
    asm volatile("ldmatrix.sync.aligned.m8n8.x4.shared.b16 {%0,%1,%2,%3}, [%4];" \
                 : "=r"(r0), "=r"(r1), "=r"(r2), "=r"(r3) : "r"(addr))

#define LDSM_X4_T(r0, r1, r2, r3, addr) \
    asm volatile("ldmatrix.sync.aligned.m8n8.x4.trans.shared.b16 {%0,%1,%2,%3}, [%4];" \
                 : "=r"(r0), "=r"(r1), "=r"(r2), "=r"(r3) : "r"(addr))

#define MMA16816(d, a, b) \
    asm volatile("mma.sync.aligned.m16n8k16.row.col.f32.bf16.bf16.f32 " \
                 "{%0,%1,%2,%3}, {%4,%5,%6,%7}, {%8,%9}, {%0,%1,%2,%3};" \
                 : "+f"((d)[0]), "+f"((d)[1]), "+f"((d)[2]), "+f"((d)[3]) \
                 : "r"((a)[0]), "r"((a)[1]), "r"((a)[2]), "r"((a)[3]), \
                   "r"((b)[0]), "r"((b)[1]))

#define CP_ASYNC16(dst, src) \
    asm volatile("cp.async.cg.shared.global [%0], [%1], 16;" :: "r"(dst), "l"(src))
#define CP_COMMIT() asm volatile("cp.async.commit_group;" ::: "memory")
#define CP_WAIT(n)  asm volatile("cp.async.wait_group %0;" :: "n"(n) : "memory")

__device__ __forceinline__ void split2(float x, float y, uint32_t& h, uint32_t& l) {
    bf16 hx = __float2bfloat16(x);
    bf16 hy = __float2bfloat16(y);
    __nv_bfloat162 H; H.x = hx; H.y = hy;
    __nv_bfloat162 L;
    L.x = __float2bfloat16(x - __bfloat162float(hx));
    L.y = __float2bfloat16(y - __bfloat162float(hy));
    h = *(uint32_t*)&H;
    l = *(uint32_t*)&L;
}

// ---------------------------------------------------------------------------
// fp32 -> (hi bf16, lo bf16) split: activations
// ---------------------------------------------------------------------------
__global__ __launch_bounds__(256) void split_bf16(
    const float4* __restrict__ in, uint2* __restrict__ hi, uint2* __restrict__ lo, int n4)
{
    int i = blockIdx.x * blockDim.x + threadIdx.x;
    if (i >= n4) return;
    float4 v = in[i];
    uint2 H, L;
    split2(v.x, v.y, H.x, L.x);
    split2(v.z, v.w, H.y, L.y);
    hi[i] = H;
    lo[i] = L;
}

// fused split of the 4 weight matrices
__global__ __launch_bounds__(256) void split_w4(
    const float4* __restrict__ w0, const float4* __restrict__ w1,
    const float4* __restrict__ w2, const float4* __restrict__ w3,
    uint2* __restrict__ h0, uint2* __restrict__ l0,
    uint2* __restrict__ h1, uint2* __restrict__ l1,
    uint2* __restrict__ h2, uint2* __restrict__ l2,
    uint2* __restrict__ h3, uint2* __restrict__ l3, int wn4)
{
    int gid = blockIdx.x * blockDim.x + threadIdx.x;
    int sel = gid / wn4;
    int i = gid - sel * wn4;
    const float4* in; uint2 *hi, *lo;
    if (sel == 0)      { in = w0; hi = h0; lo = l0; }
    else if (sel == 1) { in = w1; hi = h1; lo = l1; }
    else if (sel == 2) { in = w2; hi = h2; lo = l2; }
    else               { in = w3; hi = h3; lo = l3; }
    float4 v = in[i];
    uint2 H, L;
    split2(v.x, v.y, H.x, L.x);
    split2(v.z, v.w, H.y, L.y);
    hi[i] = H;
    lo[i] = L;
}

// ---------------------------------------------------------------------------
// mma.sync bf16x3 GEMM core: C[m][n] = sum_k A[m][k]*B[n][k] + bias[n]
// BM=BN=128, BK=32, 256 threads (8 warps, 4x2), double-buffered cp.async.
// ---------------------------------------------------------------------------
#define BKg 32
#define NKT (C_DIM / BKg)
#define ASTRIDE 40
#define SUBTILE_B (128 * ASTRIDE * 2)
#define STAGE_BYTES (4 * SUBTILE_B)
#define GEMM_SMEM (2 * STAGE_BYTES)

__device__ __forceinline__ void load_stage_g(
    const bf16* __restrict__ Ah, const bf16* __restrict__ Al,
    const bf16* __restrict__ Bh, const bf16* __restrict__ Bl,
    uint32_t smem_stage, int m0, int n0, int k0, int M, int tid)
{
    const bf16* srcs[4] = {Ah, Al, Bh, Bl};
#pragma unroll
    for (int i = 0; i < 8; i++) {
        const int c = tid + i * 256;
        const int sub = c >> 9;
        const int r = (c >> 2) & 127;
        const int cc = c & 3;
        int grow = (sub < 2 ? m0 : n0) + r;
        const int lim = (sub < 2) ? M : C_DIM;
        if (grow >= lim) grow = lim - 1;
        const void* g = srcs[sub] + (size_t)grow * C_DIM + k0 + cc * 8;
        const uint32_t d = smem_stage + sub * SUBTILE_B + r * (ASTRIDE * 2) + cc * 16;
        CP_ASYNC16(d, g);
    }
}

template <bool SPLIT_OUT>
__device__ __forceinline__ void gemm_core(
    const bf16* __restrict__ Ah, const bf16* __restrict__ Al,
    const bf16* __restrict__ Bh, const bf16* __restrict__ Bl,
    const float* __restrict__ bias, float* __restrict__ C,
    bf16* __restrict__ Oh, bf16* __restrict__ Ol, int M,
    int m0, int n0, char* dsm)
{
    const uint32_t sbase = smem_u32(dsm);
    const int tid = threadIdx.x;
    const int wid = tid >> 5;
    const int lane = tid & 31;
    const int wm = wid & 3;
    const int wn = wid >> 2;

    float acc[2][8][4];
#pragma unroll
    for (int i = 0; i < 2; i++)
#pragma unroll
        for (int j = 0; j < 8; j++)
#pragma unroll
            for (int r = 0; r < 4; r++) acc[i][j][r] = 0.0f;

    load_stage_g(Ah, Al, Bh, Bl, sbase, m0, n0, 0, M, tid);
    CP_COMMIT();
    load_stage_g(Ah, Al, Bh, Bl, sbase + STAGE_BYTES, m0, n0, BKg, M, tid);
    CP_COMMIT();

    const int a_row = (lane & 15);
    const int a_col = (lane >> 4) * 8;
    const int b_row = (lane & 7) + ((lane >> 4) & 1) * 8;
    const int b_col = ((lane >> 3) & 1) * 8;

    for (int kt = 0; kt < NKT; kt++) {
        if (kt < NKT - 1) { CP_WAIT(1); } else { CP_WAIT(0); }
        __syncthreads();
        const uint32_t st = sbase + (kt & 1) * STAGE_BYTES;

#pragma unroll
        for (int ph = 0; ph < 2; ph++) {
            const int koff = ph * 16;
            uint32_t af[2][2][4];
#pragma unroll
            for (int prod = 0; prod < 2; prod++) {
                const uint32_t abase = st + prod * SUBTILE_B;
#pragma unroll
                for (int mf = 0; mf < 2; mf++) {
                    const uint32_t addr = abase +
                        (uint32_t)((wm * 32 + mf * 16 + a_row) * (ASTRIDE * 2) +
                                   (koff + a_col) * 2);
                    LDSM_X4(af[prod][mf][0], af[prod][mf][1],
                            af[prod][mf][2], af[prod][mf][3], addr);
                }
            }
#pragma unroll
            for (int np = 0; np < 4; np++) {
                const uint32_t boff =
                    (uint32_t)((wn * 64 + np * 16 + b_row) * (ASTRIDE * 2) +
                               (koff + b_col) * 2);
                uint32_t bh[4], bl[4];
                LDSM_X4(bh[0], bh[1], bh[2], bh[3], st + 2 * SUBTILE_B + boff);
                LDSM_X4(bl[0], bl[1], bl[2], bl[3], st + 3 * SUBTILE_B + boff);
                uint32_t bh0[2] = {bh[0], bh[1]}, bh1[2] = {bh[2], bh[3]};
                uint32_t bl0[2] = {bl[0], bl[1]}, bl1[2] = {bl[2], bl[3]};
#pragma unroll
                for (int mf = 0; mf < 2; mf++) {
                    MMA16816(acc[mf][np * 2],     af[0][mf], bh0);
                    MMA16816(acc[mf][np * 2],     af[0][mf], bl0);
                    MMA16816(acc[mf][np * 2],     af[1][mf], bh0);
                    MMA16816(acc[mf][np * 2 + 1], af[0][mf], bh1);
                    MMA16816(acc[mf][np * 2 + 1], af[0][mf], bl1);
                    MMA16816(acc[mf][np * 2 + 1], af[1][mf], bh1);
                }
            }
        }
        __syncthreads();
        if (kt + 2 < NKT) {
            load_stage_g(Ah, Al, Bh, Bl, sbase + (kt & 1) * STAGE_BYTES,
                         m0, n0, (kt + 2) * BKg, M, tid);
            CP_COMMIT();
        }
    }

    const int rbase = m0 + wm * 32 + (lane >> 2);
    const int cbase = n0 + wn * 64 + (lane & 3) * 2;
#pragma unroll
    for (int mf = 0; mf < 2; mf++) {
#pragma unroll
        for (int half = 0; half < 2; half++) {
            const int row = rbase + mf * 16 + half * 8;
            if (row < M) {
#pragma unroll
                for (int nf = 0; nf < 8; nf++) {
                    const int col = cbase + nf * 8;
                    float v0 = acc[mf][nf][half * 2 + 0] + bias[col];
                    float v1 = acc[mf][nf][half * 2 + 1] + bias[col + 1];
                    if (SPLIT_OUT) {
                        uint32_t h, l;
                        split2(v0, v1, h, l);
                        *(uint32_t*)(Oh + (size_t)row * C_DIM + col) = h;
                        *(uint32_t*)(Ol + (size_t)row * C_DIM + col) = l;
                    } else {
                        float2 o; o.x = v0; o.y = v1;
                        *(float2*)(C + (size_t)row * C_DIM + col) = o;
                    }
                }
            }
        }
    }
}

// fused Q/K/V projection: blockIdx.z selects weight/output
__global__ __launch_bounds__(256, 2)
void gemm_qkv(const bf16* __restrict__ xh, const bf16* __restrict__ xl,
              const bf16* __restrict__ wqh, const bf16* __restrict__ wql,
              const float* __restrict__ bq, float* __restrict__ qo,
              const bf16* __restrict__ wkh, const bf16* __restrict__ wkl,
              const float* __restrict__ bk, float* __restrict__ ko,
              const bf16* __restrict__ wvh, const bf16* __restrict__ wvl,
              const float* __restrict__ bv,
              bf16* __restrict__ vh, bf16* __restrict__ vl, int M)
{
    extern __shared__ char dsm[];
    const int m0 = blockIdx.y * 128;
    const int n0 = blockIdx.x * 128;
    const int z = blockIdx.z;
    if (z < 2) {
        const bf16* Bh = (z == 0) ? wqh : wkh;
        const bf16* Bl = (z == 0) ? wql : wkl;
        const float* bias = (z == 0) ? bq : bk;
        float* C = (z == 0) ? qo : ko;
        gemm_core<false>(xh, xl, Bh, Bl, bias, C, nullptr, nullptr, M, m0, n0, dsm);
    } else {
        gemm_core<true>(xh, xl, wvh, wvl, bv, nullptr, vh, vl, M, m0, n0, dsm);
    }
}

// single GEMM (output projection)
__global__ __launch_bounds__(256, 2)
void gemm_single(const bf16* __restrict__ Ah, const bf16* __restrict__ Al,
                 const bf16* __restrict__ Bh, const bf16* __restrict__ Bl,
                 const float* __restrict__ bias, float* __restrict__ C, int M)
{
    extern __shared__ char dsm[];
    gemm_core<false>(Ah, Al, Bh, Bl, bias, C, nullptr, nullptr, M,
                     blockIdx.y * 128, blockIdx.x * 128, dsm);
}

// ---------------------------------------------------------------------------
// RMSNorm (fused q/k) over head dim (64) + scale + bf16 hi/lo split.
// blockIdx.y: 0 -> q (scale 0.125), 1 -> k (scale 1.0)
// ---------------------------------------------------------------------------
__global__ __launch_bounds__(256) void rmsnorm_split2(
    const float* __restrict__ qsrc, const float* __restrict__ ksrc,
    const float* __restrict__ qw, const float* __restrict__ kw,
    bf16* __restrict__ qhi, bf16* __restrict__ qlo,
    bf16* __restrict__ khi, bf16* __restrict__ klo, int nrows)
{
    int row = blockIdx.x * (blockDim.x >> 5) + (threadIdx.x >> 5);
    int lane = threadIdx.x & 31;
    if (row >= nrows) return;
    const bool isq = (blockIdx.y == 0);
    const float* src = isq ? qsrc : ksrc;
    const float* w = isq ? qw : kw;
    bf16* hi = isq ? qhi : khi;
    bf16* lo = isq ? qlo : klo;
    const float scale = isq ? 0.125f : 1.0f;

    const float* p = src + (size_t)row * HD;
    float2 x = ((const float2*)p)[lane];
    float ss = x.x * x.x + x.y * x.y;
#pragma unroll
    for (int o = 16; o > 0; o >>= 1) ss += __shfl_xor_sync(0xffffffffu, ss, o);
    float r = rsqrtf(ss * (1.0f / HD) + EPS_RMS) * scale;
    float2 wv = ((const float2*)w)[lane];
    float v0 = x.x * r * wv.x;
    float v1 = x.y * r * wv.y;
    uint32_t h, l;
    split2(v0, v1, h, l);
    *(uint32_t*)(hi + (size_t)row * HD + lane * 2) = h;
    *(uint32_t*)(lo + (size_t)row * HD + lane * 2) = l;
}

// ---------------------------------------------------------------------------
// Tensorized varlen attention (flash-2 style, bf16x3 for QK^T and P*V).
// ---------------------------------------------------------------------------
#define KSTRIDE_B 144
#define ARR_B (64 * KSTRIDE_B)
#define ATT_STAGE (4 * ARR_B)
#define ATT_SMEM (2 * ATT_STAGE)

__global__ __launch_bounds__(256, 2) void attn_mma(const int* __restrict__ cu)
{
    const int seq = blockIdx.x;
    const int head = blockIdx.y;
    const int s0 = cu[seq];
    const int L = cu[seq + 1] - s0;
    const int q0 = blockIdx.z * 128;
    if (q0 >= L) return;

    extern __shared__ char sm[];
    const uint32_t sb = smem_u32(sm);
    const int tid = threadIdx.x;
    const int wid = tid >> 5;
    const int lane = tid & 31;
    const int colh = head * HD;

    uint32_t aQh[4][4], aQl[4][4];
    {
        int r0 = q0 + wid * 16 + (lane >> 2);
        int r1 = r0 + 8;
        if (r0 >= L) r0 = L - 1;
        if (r1 >= L) r1 = L - 1;
        const size_t b0 = (size_t)(s0 + r0) * C_DIM + colh + (lane & 3) * 2;
        const size_t b1 = (size_t)(s0 + r1) * C_DIM + colh + (lane & 3) * 2;
#pragma unroll
        for (int kc = 0; kc < 4; kc++) {
            aQh[kc][0] = *(const uint32_t*)(g_qh + b0 + kc * 16);
            aQh[kc][1] = *(const uint32_t*)(g_qh + b1 + kc * 16);
            aQh[kc][2] = *(const uint32_t*)(g_qh + b0 + kc * 16 + 8);
            aQh[kc][3] = *(const uint32_t*)(g_qh + b1 + kc * 16 + 8);
            aQl[kc][0] = *(const uint32_t*)(g_ql + b0 + kc * 16);
            aQl[kc][1] = *(const uint32_t*)(g_ql + b1 + kc * 16);
            aQl[kc][2] = *(const uint32_t*)(g_ql + b0 + kc * 16 + 8);
            aQl[kc][3] = *(const uint32_t*)(g_ql + b1 + kc * 16 + 8);
        }
    }

    float o[8][4];
#pragma unroll
    for (int i = 0; i < 8; i++)
#pragma unroll
        for (int j = 0; j < 4; j++) o[i][j] = 0.0f;
    float m0 = -1e30f, m1 = -1e30f, l0 = 0.0f, l1 = 0.0f;

    const int ntiles = (L + 63) >> 6;

    auto load_tile = [&](int t) {
        const uint32_t st = sb + (t & 1) * ATT_STAGE;
        const int kb = t * 64;
        const bf16* srcs[4] = {g_kh2, g_kl2, g_vh2, g_vl2};
#pragma unroll
        for (int i = 0; i < 8; i++) {
            int c = tid + i * 256;
            int arr = c >> 9;
            int r = (c >> 3) & 63;
            int cc = c & 7;
            int key = kb + r;
            if (key >= L) key = L - 1;
            const void* g = srcs[arr] + (size_t)(s0 + key) * C_DIM + colh + cc * 8;
            CP_ASYNC16(st + arr * ARR_B + r * KSTRIDE_B + cc * 16, g);
        }
    };

    load_tile(0);
    CP_COMMIT();

    for (int t = 0; t < ntiles; t++) {
        if (t + 1 < ntiles) { load_tile(t + 1); CP_COMMIT(); CP_WAIT(1); }
        else { CP_WAIT(0); }
        __syncthreads();
        const uint32_t st = sb + (t & 1) * ATT_STAGE;
        const int kb = t * 64;

        float s[8][4];
#pragma unroll
        for (int i = 0; i < 8; i++)
#pragma unroll
            for (int j = 0; j < 4; j++) s[i][j] = 0.0f;

        const int mat = lane >> 3;
#pragma unroll
        for (int kc = 0; kc < 4; kc++) {
#pragma unroll
            for (int pair = 0; pair < 4; pair++) {
                const int krow = (pair * 2 + (mat >> 1)) * 8 + (lane & 7);
                const uint32_t cb = (uint32_t)(kc * 32 + (mat & 1) * 16);
                uint32_t kh[4], kl[4];
                LDSM_X4(kh[0], kh[1], kh[2], kh[3], st + 0     + krow * KSTRIDE_B + cb);
                LDSM_X4(kl[0], kl[1], kl[2], kl[3], st + ARR_B + krow * KSTRIDE_B + cb);
                uint32_t bh0[2] = {kh[0], kh[1]}, bh1[2] = {kh[2], kh[3]};
                uint32_t bl0[2] = {kl[0], kl[1]}, bl1[2] = {kl[2], kl[3]};
                MMA16816(s[pair * 2],     aQh[kc], bh0);
                MMA16816(s[pair * 2],     aQh[kc], bl0);
                MMA16816(s[pair * 2],     aQl[kc], bh0);
                MMA16816(s[pair * 2 + 1], aQh[kc], bh1);
                MMA16816(s[pair * 2 + 1], aQh[kc], bl1);
                MMA16816(s[pair * 2 + 1], aQl[kc], bh1);
            }
        }

        const int cb0 = (lane & 3) * 2;
#pragma unroll
        for (int nf = 0; nf < 8; nf++) {
            int colk = kb + nf * 8 + cb0;
            if (colk >= L)     { s[nf][0] = -1e30f; s[nf][2] = -1e30f; }
            if (colk + 1 >= L) { s[nf][1] = -1e30f; s[nf][3] = -1e30f; }
        }

        float mx0 = -1e30f, mx1 = -1e30f;
#pragma unroll
        for (int nf = 0; nf < 8; nf++) {
            mx0 = fmaxf(mx0, fmaxf(s[nf][0], s[nf][1]));
            mx1 = fmaxf(mx1, fmaxf(s[nf][2], s[nf][3]));
        }
        mx0 = fmaxf(mx0, __shfl_xor_sync(0xffffffffu, mx0, 1));
        mx0 = fmaxf(mx0, __shfl_xor_sync(0xffffffffu, mx0, 2));
        mx1 = fmaxf(mx1, __shfl_xor_sync(0xffffffffu, mx1, 1));
        mx1 = fmaxf(mx1, __shfl_xor_sync(0xffffffffu, mx1, 2));
        const float nm0 = fmaxf(m0, mx0);
        const float nm1 = fmaxf(m1, mx1);
        const float corr0 = __expf(m0 - nm0);
        const float corr1 = __expf(m1 - nm1);
        m0 = nm0; m1 = nm1;
        l0 *= corr0; l1 *= corr1;
#pragma unroll
        for (int nf = 0; nf < 8; nf++) {
            o[nf][0] *= corr0; o[nf][1] *= corr0;
            o[nf][2] *= corr1; o[nf][3] *= corr1;
        }
#pragma unroll
        for (int nf = 0; nf < 8; nf++) {
            s[nf][0] = __expf(s[nf][0] - m0);
            s[nf][1] = __expf(s[nf][1] - m0);
            s[nf][2] = __expf(s[nf][2] - m1);
            s[nf][3] = __expf(s[nf][3] - m1);
            l0 += s[nf][0] + s[nf][1];
            l1 += s[nf][2] + s[nf][3];
        }

#pragma unroll
        for (int j = 0; j < 4; j++) {
            uint32_t ph[4], pl[4];
            split2(s[2 * j][0], s[2 * j][1], ph[0], pl[0]);
            split2(s[2 * j][2], s[2 * j][3], ph[1], pl[1]);
            split2(s[2 * j + 1][0], s[2 * j + 1][1], ph[2], pl[2]);
            split2(s[2 * j + 1][2], s[2 * j + 1][3], ph[3], pl[3]);
            const uint32_t vrow = (uint32_t)((j * 16 + (lane & 15)) * KSTRIDE_B +
                                             ((lane >> 4) << 3) * 2);
#pragma unroll
            for (int vp = 0; vp < 4; vp++) {
                const uint32_t addr = st + 2 * ARR_B + vrow + (uint32_t)(vp * 32);
                uint32_t vh[4], vl[4];
                LDSM_X4_T(vh[0], vh[1], vh[2], vh[3], addr);
                LDSM_X4_T(vl[0], vl[1], vl[2], vl[3], addr + ARR_B);
                uint32_t bh0[2] = {vh[0], vh[1]}, bh1[2] = {vh[2], vh[3]};
                uint32_t bl0[2] = {vl[0], vl[1]}, bl1[2] = {vl[2], vl[3]};
                MMA16816(o[vp * 2],     ph, bh0);
                MMA16816(o[vp * 2],     pl, bh0);
                MMA16816(o[vp * 2],     ph, bl0);
                MMA16816(o[vp * 2 + 1], ph, bh1);
                MMA16816(o[vp * 2 + 1], pl, bh1);
                MMA16816(o[vp * 2 + 1], ph, bl1);
            }
        }
        __syncthreads();
    }

    l0 += __shfl_xor_sync(0xffffffffu, l0, 1);
    l0 += __shfl_xor_sync(0xffffffffu, l0, 2);
    l1 += __shfl_xor_sync(0xffffffffu, l1, 1);
    l1 += __shfl_xor_sync(0xffffffffu, l1, 2);
    const float inv0 = 1.0f / l0;
    const float inv1 = 1.0f / l1;
    const int r0 = q0 + wid * 16 + (lane >> 2);
    const int r1 = r0 + 8;
#pragma unroll
    for (int nf = 0; nf < 8; nf++) {
        const int col = colh + nf * 8 + (lane & 3) * 2;
        if (r0 < L) {
            uint32_t h, l;
            split2(o[nf][0] * inv0, o[nf][1] * inv0, h, l);
            *(uint32_t*)(g_ath + (size_t)(s0 + r0) * C_DIM + col) = h;
            *(uint32_t*)(g_atl + (size_t)(s0 + r0) * C_DIM + col) = l;
        }
        if (r1 < L) {
            uint32_t h, l;
            split2(o[nf][2] * inv1, o[nf][3] * inv1, h, l);
            *(uint32_t*)(g_ath + (size_t)(s0 + r1) * C_DIM + col) = h;
            *(uint32_t*)(g_atl + (size_t)(s0 + r1) * C_DIM + col) = l;
        }
    }
}

// ---------------------------------------------------------------------------
// Launch
// ---------------------------------------------------------------------------
extern "C" void kernel_launch(void* const* d_in, const int* in_sizes, int n_in,
                              void* d_out, int out_size)
{
    const float* x  = (const float*)d_in[0];
    const int* cu   = (const int*)d_in[1];
    const float* Wq = (const float*)d_in[2];
    const float* bq = (const float*)d_in[3];
    const float* Wk = (const float*)d_in[4];
    const float* bk = (const float*)d_in[5];
    const float* Wv = (const float*)d_in[6];
    const float* bv = (const float*)d_in[7];
    const float* qn = (const float*)d_in[8];
    const float* kn = (const float*)d_in[9];
    const float* Wo = (const float*)d_in[10];
    const float* bo = (const float*)d_in[11];
    float* out = (float*)d_out;

    const int T = in_sizes[0] / C_DIM;
    const int nseq = in_sizes[1] - 1;

    float *q_ptr, *k_ptr;
    cudaGetSymbolAddress((void**)&q_ptr, g_q);
    cudaGetSymbolAddress((void**)&k_ptr, g_k);
    bf16 *xh, *xl, *qh, *ql, *kh, *kl, *vh, *vl, *ath, *atl;
    bf16 *wqh, *wql, *wkh, *wkl, *wvh, *wvl, *woh, *wol;
    cudaGetSymbolAddress((void**)&xh, g_xh);
    cudaGetSymbolAddress((void**)&xl, g_xl);
    cudaGetSymbolAddress((void**)&qh, g_qh);
    cudaGetSymbolAddress((void**)&ql, g_ql);
    cudaGetSymbolAddress((void**)&kh, g_kh2);
    cudaGetSymbolAddress((void**)&kl, g_kl2);
    cudaGetSymbolAddress((void**)&vh, g_vh2);
    cudaGetSymbolAddress((void**)&vl, g_vl2);
    cudaGetSymbolAddress((void**)&ath, g_ath);
    cudaGetSymbolAddress((void**)&atl, g_atl);
    cudaGetSymbolAddress((void**)&wqh, g_wqh);
    cudaGetSymbolAddress((void**)&wql, g_wql);
    cudaGetSymbolAddress((void**)&wkh, g_wkh);
    cudaGetSymbolAddress((void**)&wkl, g_wkl);
    cudaGetSymbolAddress((void**)&wvh, g_wvh);
    cudaGetSymbolAddress((void**)&wvl, g_wvl);
    cudaGetSymbolAddress((void**)&woh, g_woh);
    cudaGetSymbolAddress((void**)&wol, g_wol);

    cudaFuncSetAttribute(gemm_qkv, cudaFuncAttributeMaxDynamicSharedMemorySize, GEMM_SMEM);
    cudaFuncSetAttribute(gemm_single, cudaFuncAttributeMaxDynamicSharedMemorySize, GEMM_SMEM);
    cudaFuncSetAttribute(attn_mma, cudaFuncAttributeMaxDynamicSharedMemorySize, ATT_SMEM);

    const int xn4 = T * C_DIM / 4;
    const int wn4 = C_DIM * C_DIM / 4;
    split_bf16<<<(xn4 + 255) / 256, 256>>>((const float4*)x, (uint2*)xh, (uint2*)xl, xn4);
    split_w4<<<(4 * wn4) / 256, 256>>>(
        (const float4*)Wq, (const float4*)Wk, (const float4*)Wv, (const float4*)Wo,
        (uint2*)wqh, (uint2*)wql, (uint2*)wkh, (uint2*)wkl,
        (uint2*)wvh, (uint2*)wvl, (uint2*)woh, (uint2*)wol, wn4);

    dim3 qkv_grid(C_DIM / 128, (T + 127) / 128, 3);
    gemm_qkv<<<qkv_grid, 256, GEMM_SMEM>>>(xh, xl,
                                           wqh, wql, bq, q_ptr,
                                           wkh, wkl, bk, k_ptr,
                                           wvh, wvl, bv, vh, vl, T);

    const int nrows = T * NH;
    dim3 rn_grid((nrows + 7) / 8, 2);
    rmsnorm_split2<<<rn_grid, 256>>>(q_ptr, k_ptr, qn, kn, qh, ql, kh, kl, nrows);

    dim3 attn_grid(nseq, NH, LMAX / 128);
    attn_mma<<<attn_grid, 256, ATT_SMEM>>>(cu);

    dim3 ggrid(C_DIM / 128, (T + 127) / 128);
    gemm_single<<<ggrid, 256, GEMM_SMEM>>>(ath, atl, woh, wol, bo, out, T);
}

// round 7
// speedup vs baseline: 3.8837x; 1.2686x over previous
#include <cuda_runtime.h>
#include <cuda_bf16.h>
#include <cstdint>

#define C_DIM 1024
#define NH 16
#define HD 64
#define MAX_T 8192
#define LMAX 1024
#define EPS_RMS 1.1920929e-07f

typedef __nv_bfloat16 bf16;

// ---------------- scratch (device globals; allocation-free rule) ----------
__device__ float g_q[MAX_T * C_DIM];
__device__ float g_k[MAX_T * C_DIM];

// linear layouts (attention operands)
__device__ bf16 g_qh[MAX_T * C_DIM];
__device__ bf16 g_ql[MAX_T * C_DIM];
__device__ bf16 g_kh2[MAX_T * C_DIM];
__device__ bf16 g_kl2[MAX_T * C_DIM];
__device__ bf16 g_vh2[MAX_T * C_DIM];
__device__ bf16 g_vl2[MAX_T * C_DIM];

// tiled layouts (GEMM operands): [blk128][kblk32][128 rows x 40 elems]
#define TROW 40
#define TBLK_ELEMS (128 * TROW)       // 5120 elems = 10240 B
#define TBLK_BYTES (TBLK_ELEMS * 2)   // 10240
#define NKB (C_DIM / 32)              // 32 k-blocks
__device__ bf16 g_xh[(MAX_T / 128) * NKB * TBLK_ELEMS];
__device__ bf16 g_xl[(MAX_T / 128) * NKB * TBLK_ELEMS];
__device__ bf16 g_ath[(MAX_T / 128) * NKB * TBLK_ELEMS];
__device__ bf16 g_atl[(MAX_T / 128) * NKB * TBLK_ELEMS];
__device__ bf16 g_wqh[8 * NKB * TBLK_ELEMS];
__device__ bf16 g_wql[8 * NKB * TBLK_ELEMS];
__device__ bf16 g_wkh[8 * NKB * TBLK_ELEMS];
__device__ bf16 g_wkl[8 * NKB * TBLK_ELEMS];
__device__ bf16 g_wvh[8 * NKB * TBLK_ELEMS];
__device__ bf16 g_wvl[8 * NKB * TBLK_ELEMS];
__device__ bf16 g_woh[8 * NKB * TBLK_ELEMS];
__device__ bf16 g_wol[8 * NKB * TBLK_ELEMS];

// ---------------- helpers ---------------------------------------------
__device__ __forceinline__ uint32_t smem_u32(const void* p) {
    uint32_t a;
    asm("{ .reg .u64 t; cvta.to.shared.u64 t, %1; cvt.u32.u64 %0, t; }"
        : "=r"(a) : "l"(p));
    return a;
}

// element offset of (row r, col c) in the tiled layout
__device__ __forceinline__ size_t tiled_off(int r, int c) {
    return ((size_t)((r >> 7) * NKB + (c >> 5))) * TBLK_ELEMS +
           (size_t)((r & 127) * TROW + (c & 31));
}

#define LDSM_X4(r0, r1, r2, r3, addr) \
    asm volatile("ldmatrix.sync.aligned.m8n8.x4.shared.b16 {%0,%1,%2,%3}, [%4];" \
                 : "=r"(r0), "=r"(r1), "=r"(r2), "=r"(r3) : "r"(addr))

#define LDSM_X4_T(r0, r1, r2, r3, addr) \
    asm volatile("ldmatrix.sync.aligned.m8n8.x4.trans.shared.b16 {%0,%1,%2,%3}, [%4];" \
                 : "=r"(r0), "=r"(r1), "=r"(r2), "=r"(r3) : "r"(addr))

#define MMA16816(d, a, b) \
    asm volatile("mma.sync.aligned.m16n8k16.row.col.f32.bf16.bf16.f32 " \
                 "{%0,%1,%2,%3}, {%4,%5,%6,%7}, {%8,%9}, {%0,%1,%2,%3};" \
                 : "+f"((d)[0]), "+f"((d)[1]), "+f"((d)[2]), "+f"((d)[3]) \
                 : "r"((a)[0]), "r"((a)[1]), "r"((a)[2]), "r"((a)[3]), \
                   "r"((b)[0]), "r"((b)[1]))

#define CP_ASYNC16(dst, src) \
    asm volatile("cp.async.cg.shared.global [%0], [%1], 16;" :: "r"(dst), "l"(src))
#define CP_COMMIT() asm volatile("cp.async.commit_group;" ::: "memory")
#define CP_WAIT(n)  asm volatile("cp.async.wait_group %0;" :: "n"(n) : "memory")

#define MBAR_INIT(a, cnt) \
    asm volatile("mbarrier.init.shared.b64 [%0], %1;" :: "r"(a), "r"(cnt) : "memory")
#define MBAR_EXPECT_TX(a, bytes) \
    asm volatile("mbarrier.arrive.expect_tx.shared.b64 _, [%0], %1;" \
                 :: "r"(a), "r"(bytes) : "memory")
#define BULK_G2S(dst, src, bytes, mbar) \
    asm volatile("cp.async.bulk.shared::cta.global.mbarrier::complete_tx::bytes " \
                 "[%0], [%1], %2, [%3];" \
                 :: "r"(dst), "l"(src), "r"(bytes), "r"(mbar) : "memory")

__device__ __forceinline__ void mbar_wait(uint32_t a, int phase) {
    asm volatile(
        "{ .reg .pred P;\n"
        "WL%=:\n"
        " mbarrier.try_wait.parity.acquire.cta.shared::cta.b64 P, [%0], %1, 0x989680;\n"
        " @P bra WD%=;\n"
        " bra WL%=;\n"
        "WD%=: }"
        :: "r"(a), "r"(phase) : "memory");
}

__device__ __forceinline__ void split2(float x, float y, uint32_t& h, uint32_t& l) {
    bf16 hx = __float2bfloat16(x);
    bf16 hy = __float2bfloat16(y);
    __nv_bfloat162 H; H.x = hx; H.y = hy;
    __nv_bfloat162 L;
    L.x = __float2bfloat16(x - __bfloat162float(hx));
    L.y = __float2bfloat16(y - __bfloat162float(hy));
    h = *(uint32_t*)&H;
    l = *(uint32_t*)&L;
}

// ---------------------------------------------------------------------------
// fp32 -> (hi,lo) split into TILED layout (x / attention-out A operands, weights)
// ---------------------------------------------------------------------------
__global__ __launch_bounds__(256) void split_x_tiled(
    const float4* __restrict__ in, bf16* __restrict__ hi, bf16* __restrict__ lo, int n4)
{
    int i = blockIdx.x * blockDim.x + threadIdx.x;
    if (i >= n4) return;
    float4 v = in[i];
    const int row = i >> 8;             // 256 float4 per 1024-col row
    const int c = (i & 255) * 4;
    const size_t off = tiled_off(row, c);
    uint32_t h0, l0, h1, l1;
    split2(v.x, v.y, h0, l0);
    split2(v.z, v.w, h1, l1);
    *(uint2*)(hi + off) = make_uint2(h0, h1);
    *(uint2*)(lo + off) = make_uint2(l0, l1);
}

__global__ __launch_bounds__(256) void split_w4_tiled(
    const float4* __restrict__ w0, const float4* __restrict__ w1,
    const float4* __restrict__ w2, const float4* __restrict__ w3,
    bf16* __restrict__ h0p, bf16* __restrict__ l0p,
    bf16* __restrict__ h1p, bf16* __restrict__ l1p,
    bf16* __restrict__ h2p, bf16* __restrict__ l2p,
    bf16* __restrict__ h3p, bf16* __restrict__ l3p, int wn4)
{
    int gid = blockIdx.x * blockDim.x + threadIdx.x;
    int sel = gid / wn4;
    int i = gid - sel * wn4;
    const float4* in; bf16 *hi, *lo;
    if (sel == 0)      { in = w0; hi = h0p; lo = l0p; }
    else if (sel == 1) { in = w1; hi = h1p; lo = l1p; }
    else if (sel == 2) { in = w2; hi = h2p; lo = l2p; }
    else               { in = w3; hi = h3p; lo = l3p; }
    float4 v = in[i];
    const int row = i >> 8;
    const int c = (i & 255) * 4;
    const size_t off = tiled_off(row, c);
    uint32_t a0, b0, a1, b1;
    split2(v.x, v.y, a0, b0);
    split2(v.z, v.w, a1, b1);
    *(uint2*)(hi + off) = make_uint2(a0, a1);
    *(uint2*)(lo + off) = make_uint2(b0, b1);
}

// ---------------------------------------------------------------------------
// bulk-copy bf16x3 GEMM core: C[m][n] = sum_k A[m][k]*B[n][k] + bias[n]
// Operands in tiled layout. BM=BN=128, BK=32, 256 threads, double buffer.
// ---------------------------------------------------------------------------
#define NKT NKB
#define SUBTILE_B TBLK_BYTES              // 10240
#define STAGE_BYTES (4 * SUBTILE_B)       // 40960 (Ah, Al, Bh, Bl)
#define GEMM_SMEM (128 + 2 * STAGE_BYTES) // 82048

template <bool SPLIT_OUT>
__device__ __forceinline__ void gemm_core(
    const bf16* __restrict__ Ah, const bf16* __restrict__ Al,
    const bf16* __restrict__ Bh, const bf16* __restrict__ Bl,
    const float* __restrict__ bias, float* __restrict__ C,
    bf16* __restrict__ Oh, bf16* __restrict__ Ol, int M,
    int mblk, int nblk, char* dsm)
{
    const uint32_t sbase = smem_u32(dsm);
    const uint32_t mb0 = sbase, mb1 = sbase + 8;
    const uint32_t tiles = sbase + 128;
    const int tid = threadIdx.x;
    const int wid = tid >> 5;
    const int lane = tid & 31;
    const int wm = wid & 3;
    const int wn = wid >> 2;

    float acc[2][8][4];
#pragma unroll
    for (int i = 0; i < 2; i++)
#pragma unroll
        for (int j = 0; j < 8; j++)
#pragma unroll
            for (int r = 0; r < 4; r++) acc[i][j][r] = 0.0f;

    if (tid == 0) { MBAR_INIT(mb0, 1); MBAR_INIT(mb1, 1); }
    __syncthreads();

    const size_t abase_blk = (size_t)mblk * NKB;
    const size_t bbase_blk = (size_t)nblk * NKB;

    auto issue = [&](int kt) {
        const int s = kt & 1;
        const uint32_t dst = tiles + s * STAGE_BYTES;
        const uint32_t m = s ? mb1 : mb0;
        MBAR_EXPECT_TX(m, (uint32_t)STAGE_BYTES);
        const size_t ao = (abase_blk + kt) * TBLK_ELEMS;
        const size_t bo = (bbase_blk + kt) * TBLK_ELEMS;
        BULK_G2S(dst,                  Ah + ao, (uint32_t)TBLK_BYTES, m);
        BULK_G2S(dst + SUBTILE_B,      Al + ao, (uint32_t)TBLK_BYTES, m);
        BULK_G2S(dst + 2 * SUBTILE_B,  Bh + bo, (uint32_t)TBLK_BYTES, m);
        BULK_G2S(dst + 3 * SUBTILE_B,  Bl + bo, (uint32_t)TBLK_BYTES, m);
    };
    if (tid == 0) { issue(0); issue(1); }

    const int a_row = (lane & 15);
    const int a_col = (lane >> 4) * 8;
    const int b_row = (lane & 7) + ((lane >> 4) & 1) * 8;
    const int b_col = ((lane >> 3) & 1) * 8;

    int ph0 = 0, ph1 = 0;
    for (int kt = 0; kt < NKT; kt++) {
        const int s = kt & 1;
        if (s == 0) { mbar_wait(mb0, ph0); ph0 ^= 1; }
        else        { mbar_wait(mb1, ph1); ph1 ^= 1; }
        const uint32_t st = tiles + s * STAGE_BYTES;

#pragma unroll
        for (int ph = 0; ph < 2; ph++) {
            const int koff = ph * 16;
            uint32_t af[2][2][4];
#pragma unroll
            for (int prod = 0; prod < 2; prod++) {
                const uint32_t abase = st + prod * SUBTILE_B;
#pragma unroll
                for (int mf = 0; mf < 2; mf++) {
                    const uint32_t addr = abase +
                        (uint32_t)((wm * 32 + mf * 16 + a_row) * (TROW * 2) +
                                   (koff + a_col) * 2);
                    LDSM_X4(af[prod][mf][0], af[prod][mf][1],
                            af[prod][mf][2], af[prod][mf][3], addr);
                }
            }
#pragma unroll
            for (int np = 0; np < 4; np++) {
                const uint32_t boff =
                    (uint32_t)((wn * 64 + np * 16 + b_row) * (TROW * 2) +
                               (koff + b_col) * 2);
                uint32_t bh[4], bl[4];
                LDSM_X4(bh[0], bh[1], bh[2], bh[3], st + 2 * SUBTILE_B + boff);
                LDSM_X4(bl[0], bl[1], bl[2], bl[3], st + 3 * SUBTILE_B + boff);
                uint32_t bh0[2] = {bh[0], bh[1]}, bh1[2] = {bh[2], bh[3]};
                uint32_t bl0[2] = {bl[0], bl[1]}, bl1[2] = {bl[2], bl[3]};
#pragma unroll
                for (int mf = 0; mf < 2; mf++) {
                    MMA16816(acc[mf][np * 2],     af[0][mf], bh0);
                    MMA16816(acc[mf][np * 2],     af[0][mf], bl0);
                    MMA16816(acc[mf][np * 2],     af[1][mf], bh0);
                    MMA16816(acc[mf][np * 2 + 1], af[0][mf], bh1);
                    MMA16816(acc[mf][np * 2 + 1], af[0][mf], bl1);
                    MMA16816(acc[mf][np * 2 + 1], af[1][mf], bh1);
                }
            }
        }
        __syncthreads();
        if (kt + 2 < NKT && tid == 0) issue(kt + 2);
    }

    const int m0 = mblk * 128, n0 = nblk * 128;
    const int rbase = m0 + wm * 32 + (lane >> 2);
    const int cbase = n0 + wn * 64 + (lane & 3) * 2;
#pragma unroll
    for (int mf = 0; mf < 2; mf++) {
#pragma unroll
        for (int half = 0; half < 2; half++) {
            const int row = rbase + mf * 16 + half * 8;
            if (row < M) {
#pragma unroll
                for (int nf = 0; nf < 8; nf++) {
                    const int col = cbase + nf * 8;
                    float v0 = acc[mf][nf][half * 2 + 0] + bias[col];
                    float v1 = acc[mf][nf][half * 2 + 1] + bias[col + 1];
                    if (SPLIT_OUT) {
                        uint32_t h, l;
                        split2(v0, v1, h, l);
                        *(uint32_t*)(Oh + (size_t)row * C_DIM + col) = h;
                        *(uint32_t*)(Ol + (size_t)row * C_DIM + col) = l;
                    } else {
                        float2 o; o.x = v0; o.y = v1;
                        *(float2*)(C + (size_t)row * C_DIM + col) = o;
                    }
                }
            }
        }
    }
}

__global__ __launch_bounds__(256, 2)
void gemm_qkv(const bf16* __restrict__ xh, const bf16* __restrict__ xl,
              const bf16* __restrict__ wqh, const bf16* __restrict__ wql,
              const float* __restrict__ bq, float* __restrict__ qo,
              const bf16* __restrict__ wkh, const bf16* __restrict__ wkl,
              const float* __restrict__ bk, float* __restrict__ ko,
              const bf16* __restrict__ wvh, const bf16* __restrict__ wvl,
              const float* __restrict__ bv,
              bf16* __restrict__ vh, bf16* __restrict__ vl, int M)
{
    extern __shared__ char dsm[];
    const int z = blockIdx.z;
    if (z < 2) {
        const bf16* Bh = (z == 0) ? wqh : wkh;
        const bf16* Bl = (z == 0) ? wql : wkl;
        const float* bias = (z == 0) ? bq : bk;
        float* C = (z == 0) ? qo : ko;
        gemm_core<false>(xh, xl, Bh, Bl, bias, C, nullptr, nullptr, M,
                         blockIdx.y, blockIdx.x, dsm);
    } else {
        gemm_core<true>(xh, xl, wvh, wvl, bv, nullptr, vh, vl, M,
                        blockIdx.y, blockIdx.x, dsm);
    }
}

__global__ __launch_bounds__(256, 2)
void gemm_single(const bf16* __restrict__ Ah, const bf16* __restrict__ Al,
                 const bf16* __restrict__ Bh, const bf16* __restrict__ Bl,
                 const float* __restrict__ bias, float* __restrict__ C, int M)
{
    extern __shared__ char dsm[];
    gemm_core<false>(Ah, Al, Bh, Bl, bias, C, nullptr, nullptr, M,
                     blockIdx.y, blockIdx.x, dsm);
}

// ---------------------------------------------------------------------------
// RMSNorm (fused q/k) + scale + bf16 hi/lo split (linear layout for attention)
// ---------------------------------------------------------------------------
__global__ __launch_bounds__(256) void rmsnorm_split2(
    const float* __restrict__ qsrc, const float* __restrict__ ksrc,
    const float* __restrict__ qw, const float* __restrict__ kw,
    bf16* __restrict__ qhi, bf16* __restrict__ qlo,
    bf16* __restrict__ khi, bf16* __restrict__ klo, int nrows)
{
    int row = blockIdx.x * (blockDim.x >> 5) + (threadIdx.x >> 5);
    int lane = threadIdx.x & 31;
    if (row >= nrows) return;
    const bool isq = (blockIdx.y == 0);
    const float* src = isq ? qsrc : ksrc;
    const float* w = isq ? qw : kw;
    bf16* hi = isq ? qhi : khi;
    bf16* lo = isq ? qlo : klo;
    const float scale = isq ? 0.125f : 1.0f;

    const float* p = src + (size_t)row * HD;
    float2 x = ((const float2*)p)[lane];
    float ss = x.x * x.x + x.y * x.y;
#pragma unroll
    for (int o = 16; o > 0; o >>= 1) ss += __shfl_xor_sync(0xffffffffu, ss, o);
    float r = rsqrtf(ss * (1.0f / HD) + EPS_RMS) * scale;
    float2 wv = ((const float2*)w)[lane];
    float v0 = x.x * r * wv.x;
    float v1 = x.y * r * wv.y;
    uint32_t h, l;
    split2(v0, v1, h, l);
    *(uint32_t*)(hi + (size_t)row * HD + lane * 2) = h;
    *(uint32_t*)(lo + (size_t)row * HD + lane * 2) = l;
}

// ---------------------------------------------------------------------------
// Tensorized varlen attention (flash-2, bf16x3); epilogue writes TILED layout
// ---------------------------------------------------------------------------
#define KSTRIDE_B 144
#define ARR_B (64 * KSTRIDE_B)
#define ATT_STAGE (4 * ARR_B)
#define ATT_SMEM (2 * ATT_STAGE)

__global__ __launch_bounds__(256, 2) void attn_mma(const int* __restrict__ cu)
{
    const int seq = blockIdx.x;
    const int head = blockIdx.y;
    const int s0 = cu[seq];
    const int L = cu[seq + 1] - s0;
    const int q0 = blockIdx.z * 128;
    if (q0 >= L) return;

    extern __shared__ char sm[];
    const uint32_t sb = smem_u32(sm);
    const int tid = threadIdx.x;
    const int wid = tid >> 5;
    const int lane = tid & 31;
    const int colh = head * HD;

    uint32_t aQh[4][4], aQl[4][4];
    {
        int r0 = q0 + wid * 16 + (lane >> 2);
        int r1 = r0 + 8;
        if (r0 >= L) r0 = L - 1;
        if (r1 >= L) r1 = L - 1;
        const size_t b0 = (size_t)(s0 + r0) * C_DIM + colh + (lane & 3) * 2;
        const size_t b1 = (size_t)(s0 + r1) * C_DIM + colh + (lane & 3) * 2;
#pragma unroll
        for (int kc = 0; kc < 4; kc++) {
            aQh[kc][0] = *(const uint32_t*)(g_qh + b0 + kc * 16);
            aQh[kc][1] = *(const uint32_t*)(g_qh + b1 + kc * 16);
            aQh[kc][2] = *(const uint32_t*)(g_qh + b0 + kc * 16 + 8);
            aQh[kc][3] = *(const uint32_t*)(g_qh + b1 + kc * 16 + 8);
            aQl[kc][0] = *(const uint32_t*)(g_ql + b0 + kc * 16);
            aQl[kc][1] = *(const uint32_t*)(g_ql + b1 + kc * 16);
            aQl[kc][2] = *(const uint32_t*)(g_ql + b0 + kc * 16 + 8);
            aQl[kc][3] = *(const uint32_t*)(g_ql + b1 + kc * 16 + 8);
        }
    }

    float o[8][4];
#pragma unroll
    for (int i = 0; i < 8; i++)
#pragma unroll
        for (int j = 0; j < 4; j++) o[i][j] = 0.0f;
    float m0 = -1e30f, m1 = -1e30f, l0 = 0.0f, l1 = 0.0f;

    const int ntiles = (L + 63) >> 6;

    auto load_tile = [&](int t) {
        const uint32_t st = sb + (t & 1) * ATT_STAGE;
        const int kb = t * 64;
        const bf16* srcs[4] = {g_kh2, g_kl2, g_vh2, g_vl2};
#pragma unroll
        for (int i = 0; i < 8; i++) {
            int c = tid + i * 256;
            int arr = c >> 9;
            int r = (c >> 3) & 63;
            int cc = c & 7;
            int key = kb + r;
            if (key >= L) key = L - 1;
            const void* g = srcs[arr] + (size_t)(s0 + key) * C_DIM + colh + cc * 8;
            CP_ASYNC16(st + arr * ARR_B + r * KSTRIDE_B + cc * 16, g);
        }
    };

    load_tile(0);
    CP_COMMIT();

    for (int t = 0; t < ntiles; t++) {
        if (t + 1 < ntiles) { load_tile(t + 1); CP_COMMIT(); CP_WAIT(1); }
        else { CP_WAIT(0); }
        __syncthreads();
        const uint32_t st = sb + (t & 1) * ATT_STAGE;
        const int kb = t * 64;

        float s[8][4];
#pragma unroll
        for (int i = 0; i < 8; i++)
#pragma unroll
            for (int j = 0; j < 4; j++) s[i][j] = 0.0f;

        const int mat = lane >> 3;
#pragma unroll
        for (int kc = 0; kc < 4; kc++) {
#pragma unroll
            for (int pair = 0; pair < 4; pair++) {
                const int krow = (pair * 2 + (mat >> 1)) * 8 + (lane & 7);
                const uint32_t cb = (uint32_t)(kc * 32 + (mat & 1) * 16);
                uint32_t kh[4], kl[4];
                LDSM_X4(kh[0], kh[1], kh[2], kh[3], st + 0     + krow * KSTRIDE_B + cb);
                LDSM_X4(kl[0], kl[1], kl[2], kl[3], st + ARR_B + krow * KSTRIDE_B + cb);
                uint32_t bh0[2] = {kh[0], kh[1]}, bh1[2] = {kh[2], kh[3]};
                uint32_t bl0[2] = {kl[0], kl[1]}, bl1[2] = {kl[2], kl[3]};
                MMA16816(s[pair * 2],     aQh[kc], bh0);
                MMA16816(s[pair * 2],     aQh[kc], bl0);
                MMA16816(s[pair * 2],     aQl[kc], bh0);
                MMA16816(s[pair * 2 + 1], aQh[kc], bh1);
                MMA16816(s[pair * 2 + 1], aQh[kc], bl1);
                MMA16816(s[pair * 2 + 1], aQl[kc], bh1);
            }
        }

        const int cb0 = (lane & 3) * 2;
#pragma unroll
        for (int nf = 0; nf < 8; nf++) {
            int colk = kb + nf * 8 + cb0;
            if (colk >= L)     { s[nf][0] = -1e30f; s[nf][2] = -1e30f; }
            if (colk + 1 >= L) { s[nf][1] = -1e30f; s[nf][3] = -1e30f; }
        }

        float mx0 = -1e30f, mx1 = -1e30f;
#pragma unroll
        for (int nf = 0; nf < 8; nf++) {
            mx0 = fmaxf(mx0, fmaxf(s[nf][0], s[nf][1]));
            mx1 = fmaxf(mx1, fmaxf(s[nf][2], s[nf][3]));
        }
        mx0 = fmaxf(mx0, __shfl_xor_sync(0xffffffffu, mx0, 1));
        mx0 = fmaxf(mx0, __shfl_xor_sync(0xffffffffu, mx0, 2));
        mx1 = fmaxf(mx1, __shfl_xor_sync(0xffffffffu, mx1, 1));
        mx1 = fmaxf(mx1, __shfl_xor_sync(0xffffffffu, mx1, 2));
        const float nm0 = fmaxf(m0, mx0);
        const float nm1 = fmaxf(m1, mx1);
        const float corr0 = __expf(m0 - nm0);
        const float corr1 = __expf(m1 - nm1);
        m0 = nm0; m1 = nm1;
        l0 *= corr0; l1 *= corr1;
#pragma unroll
        for (int nf = 0; nf < 8; nf++) {
            o[nf][0] *= corr0; o[nf][1] *= corr0;
            o[nf][2] *= corr1; o[nf][3] *= corr1;
        }
#pragma unroll
        for (int nf = 0; nf < 8; nf++) {
            s[nf][0] = __expf(s[nf][0] - m0);
            s[nf][1] = __expf(s[nf][1] - m0);
            s[nf][2] = __expf(s[nf][2] - m1);
            s[nf][3] = __expf(s[nf][3] - m1);
            l0 += s[nf][0] + s[nf][1];
            l1 += s[nf][2] + s[nf][3];
        }

#pragma unroll
        for (int j = 0; j < 4; j++) {
            uint32_t ph[4], pl[4];
            split2(s[2 * j][0], s[2 * j][1], ph[0], pl[0]);
            split2(s[2 * j][2], s[2 * j][3], ph[1], pl[1]);
            split2(s[2 * j + 1][0], s[2 * j + 1][1], ph[2], pl[2]);
            split2(s[2 * j + 1][2], s[2 * j + 1][3], ph[3], pl[3]);
            const uint32_t vrow = (uint32_t)((j * 16 + (lane & 15)) * KSTRIDE_B +
                                             ((lane >> 4) << 3) * 2);
#pragma unroll
            for (int vp = 0; vp < 4; vp++) {
                const uint32_t addr = st + 2 * ARR_B + vrow + (uint32_t)(vp * 32);
                uint32_t vh[4], vl[4];
                LDSM_X4_T(vh[0], vh[1], vh[2], vh[3], addr);
                LDSM_X4_T(vl[0], vl[1], vl[2], vl[3], addr + ARR_B);
                uint32_t bh0[2] = {vh[0], vh[1]}, bh1[2] = {vh[2], vh[3]};
                uint32_t bl0[2] = {vl[0], vl[1]}, bl1[2] = {vl[2], vl[3]};
                MMA16816(o[vp * 2],     ph, bh0);
                MMA16816(o[vp * 2],     pl, bh0);
                MMA16816(o[vp * 2],     ph, bl0);
                MMA16816(o[vp * 2 + 1], ph, bh1);
                MMA16816(o[vp * 2 + 1], pl, bh1);
                MMA16816(o[vp * 2 + 1], ph, bl1);
            }
        }
        __syncthreads();
    }

    l0 += __shfl_xor_sync(0xffffffffu, l0, 1);
    l0 += __shfl_xor_sync(0xffffffffu, l0, 2);
    l1 += __shfl_xor_sync(0xffffffffu, l1, 1);
    l1 += __shfl_xor_sync(0xffffffffu, l1, 2);
    const float inv0 = 1.0f / l0;
    const float inv1 = 1.0f / l1;
    const int r0 = q0 + wid * 16 + (lane >> 2);
    const int r1 = r0 + 8;
#pragma unroll
    for (int nf = 0; nf < 8; nf++) {
        const int col = colh + nf * 8 + (lane & 3) * 2;
        if (r0 < L) {
            uint32_t h, l;
            split2(o[nf][0] * inv0, o[nf][1] * inv0, h, l);
            const size_t off = tiled_off(s0 + r0, col);
            *(uint32_t*)(g_ath + off) = h;
            *(uint32_t*)(g_atl + off) = l;
        }
        if (r1 < L) {
            uint32_t h, l;
            split2(o[nf][2] * inv1, o[nf][3] * inv1, h, l);
            const size_t off = tiled_off(s0 + r1, col);
            *(uint32_t*)(g_ath + off) = h;
            *(uint32_t*)(g_atl + off) = l;
        }
    }
}

// ---------------------------------------------------------------------------
// Launch
// ---------------------------------------------------------------------------
extern "C" void kernel_launch(void* const* d_in, const int* in_sizes, int n_in,
                              void* d_out, int out_size)
{
    const float* x  = (const float*)d_in[0];
    const int* cu   = (const int*)d_in[1];
    const float* Wq = (const float*)d_in[2];
    const float* bq = (const float*)d_in[3];
    const float* Wk = (const float*)d_in[4];
    const float* bk = (const float*)d_in[5];
    const float* Wv = (const float*)d_in[6];
    const float* bv = (const float*)d_in[7];
    const float* qn = (const float*)d_in[8];
    const float* kn = (const float*)d_in[9];
    const float* Wo = (const float*)d_in[10];
    const float* bo = (const float*)d_in[11];
    float* out = (float*)d_out;

    const int T = in_sizes[0] / C_DIM;
    const int nseq = in_sizes[1] - 1;

    float *q_ptr, *k_ptr;
    cudaGetSymbolAddress((void**)&q_ptr, g_q);
    cudaGetSymbolAddress((void**)&k_ptr, g_k);
    bf16 *xh, *xl, *qh, *ql, *kh, *kl, *vh, *vl, *ath, *atl;
    bf16 *wqh, *wql, *wkh, *wkl, *wvh, *wvl, *woh, *wol;
    cudaGetSymbolAddress((void**)&xh, g_xh);
    cudaGetSymbolAddress((void**)&xl, g_xl);
    cudaGetSymbolAddress((void**)&qh, g_qh);
    cudaGetSymbolAddress((void**)&ql, g_ql);
    cudaGetSymbolAddress((void**)&kh, g_kh2);
    cudaGetSymbolAddress((void**)&kl, g_kl2);
    cudaGetSymbolAddress((void**)&vh, g_vh2);
    cudaGetSymbolAddress((void**)&vl, g_vl2);
    cudaGetSymbolAddress((void**)&ath, g_ath);
    cudaGetSymbolAddress((void**)&atl, g_atl);
    cudaGetSymbolAddress((void**)&wqh, g_wqh);
    cudaGetSymbolAddress((void**)&wql, g_wql);
    cudaGetSymbolAddress((void**)&wkh, g_wkh);
    cudaGetSymbolAddress((void**)&wkl, g_wkl);
    cudaGetSymbolAddress((void**)&wvh, g_wvh);
    cudaGetSymbolAddress((void**)&wvl, g_wvl);
    cudaGetSymbolAddress((void**)&woh, g_woh);
    cudaGetSymbolAddress((void**)&wol, g_wol);

    cudaFuncSetAttribute(gemm_qkv, cudaFuncAttributeMaxDynamicSharedMemorySize, GEMM_SMEM);
    cudaFuncSetAttribute(gemm_single, cudaFuncAttributeMaxDynamicSharedMemorySize, GEMM_SMEM);
    cudaFuncSetAttribute(attn_mma, cudaFuncAttributeMaxDynamicSharedMemorySize, ATT_SMEM);

    const int xn4 = T * C_DIM / 4;
    const int wn4 = C_DIM * C_DIM / 4;
    split_x_tiled<<<(xn4 + 255) / 256, 256>>>((const float4*)x, xh, xl, xn4);
    split_w4_tiled<<<(4 * wn4) / 256, 256>>>(
        (const float4*)Wq, (const float4*)Wk, (const float4*)Wv, (const float4*)Wo,
        wqh, wql, wkh, wkl, wvh, wvl, woh, wol, wn4);

    dim3 qkv_grid(C_DIM / 128, (T + 127) / 128, 3);
    gemm_qkv<<<qkv_grid, 256, GEMM_SMEM>>>(xh, xl,
                                           wqh, wql, bq, q_ptr,
                                           wkh, wkl, bk, k_ptr,
                                           wvh, wvl, bv, vh, vl, T);

    const int nrows = T * NH;
    dim3 rn_grid((nrows + 7) / 8, 2);
    rmsnorm_split2<<<rn_grid, 256>>>(q_ptr, k_ptr, qn, kn, qh, ql, kh, kl, nrows);

    dim3 attn_grid(nseq, NH, LMAX / 128);
    attn_mma<<<attn_grid, 256, ATT_SMEM>>>(cu);

    dim3 ggrid(C_DIM / 128, (T + 127) / 128);
    gemm_single<<<ggrid, 256, GEMM_SMEM>>>(ath, atl, woh, wol, bo, out, T);
}